// round 7
// baseline (speedup 1.0000x reference)
#include <cuda_runtime.h>
#include <math.h>
#include <stdint.h>

// Problem constants
#define Bq 64
#define Tq 512
#define Iq 512
#define Hq 1024
#define Gq 4096      // 4*H
#define Cq 20
#define MTOT (Bq*Tq) // 32768
#define NBLK 128     // persistent blocks (<148 => all co-resident)

// lstm_layer shared-memory layout (floats)
#define WPAD 1028                 // 1024 + 4
#define HPAD 132                  // 128 + 4
#define HBUF (64*HPAD)            // one h chunk buffer: 8448 floats
#define WOFF 0                    // weights: 32 x WPAD = 32896
#define HOFF (32*WPAD)            // h double buffer: 2*HBUF = 16896
#define GOFF (HOFF + 2*HBUF)      // gate tile: 64 x 36 = 2304
#define SMEM_FLOATS (GOFF + 64*36)
#define SMEM_BYTES (SMEM_FLOATS * 4)

// ---- scratch (static device allocations; no cudaMalloc allowed) ----
__device__ float g_xproj[(size_t)MTOT * Gq];   // 512 MB, reused by both layers
__device__ float g_hseq1[(size_t)MTOT * Hq];   // 134 MB (T,B,H)
__device__ float g_hseq2[(size_t)MTOT * Hq];   // 134 MB (T,B,H)
__device__ float g_hbuf[2][Bq * Hq];           // h ping-pong
__device__ float g_emis[(size_t)MTOT * Cq];    // (T,B,C)
__device__ float g_llh[Bq];
__device__ unsigned g_cnt;
__device__ unsigned g_phase;

// ---- packed f32x2 helpers (FFMA2: 2x fp32 FMA per instruction) ----
__device__ __forceinline__ unsigned long long ffma2(unsigned long long a,
                                                    unsigned long long b,
                                                    unsigned long long c)
{
    unsigned long long d;
    asm("fma.rn.f32x2 %0, %1, %2, %3;" : "=l"(d) : "l"(a), "l"(b), "l"(c));
    return d;
}
__device__ __forceinline__ float u64lo(unsigned long long v)
{
    return __uint_as_float((unsigned)(v & 0xffffffffull));
}
__device__ __forceinline__ float u64hi(unsigned long long v)
{
    return __uint_as_float((unsigned)(v >> 32));
}

__device__ __forceinline__ void cp_async16(void* smem_dst, const void* gmem_src)
{
    uint32_t s = (uint32_t)__cvta_generic_to_shared(smem_dst);
    asm volatile("cp.async.cg.shared.global [%0], [%1], 16;\n" :: "r"(s), "l"(gmem_src));
}
__device__ __forceinline__ void cp_commit()
{
    asm volatile("cp.async.commit_group;\n");
}
__device__ __forceinline__ void cp_wait0()
{
    asm volatile("cp.async.wait_group 0;\n");
}

// ============================================================
// 128x128x(BK=16) fp32 SGEMM with FFMA2: Y = X(MxK)*W(NxK)^T + bias
// grid (N/128, M/128), 512 threads (16 warps, 4/SMSP).
// Per thread: 8m x 4n with n = tx + 16j + 64*nhalf.
// Tiles k-contiguous in smem ([row][20]), cp.async double-buffered.
// If remap!=0, X row m = b*T+t and output row becomes t*B+b.
// ============================================================
__global__ void __launch_bounds__(512, 1)
sgemm128(const float* __restrict__ X, const float* __restrict__ W,
         const float* __restrict__ bias, float* __restrict__ Y,
         int K, int remap)
{
    __shared__ float Xs[2][128][20];
    __shared__ float Ws[2][128][20];
    const int bn = blockIdx.x * 128;
    const int bm = blockIdx.y * 128;
    const int tid = threadIdx.x;
    const int nh = tid >> 8;          // 0/1 n-half
    const int my = (tid >> 4) & 15;   // m0 = my*8
    const int tx = tid & 15;          // n cols: tx + 16j + 64nh

    // tile-load coords (1 float4 per thread per tile per operand)
    const int lr = tid >> 2;          // 0..127
    const int lk = (tid & 3) * 4;

    unsigned long long acc2[8][4] = {};

    // prefetch tile 0
    cp_async16(&Xs[0][lr][lk], X + (size_t)(bm + lr) * K + lk);
    cp_async16(&Ws[0][lr][lk], W + (size_t)(bn + lr) * K + lk);
    cp_commit();

    const int nb = K >> 4;
    for (int kb = 0; kb < nb; kb++) {
        const int buf = kb & 1;
        cp_wait0();
        __syncthreads();
        if (kb + 1 < nb) {
            int k0 = (kb + 1) << 4;
            cp_async16(&Xs[buf ^ 1][lr][lk], X + (size_t)(bm + lr) * K + k0 + lk);
            cp_async16(&Ws[buf ^ 1][lr][lk], W + (size_t)(bn + lr) * K + k0 + lk);
            cp_commit();
        }

        #pragma unroll
        for (int kk = 0; kk < 16; kk += 4) {
            ulonglong2 aq[8], wq[4];
            #pragma unroll
            for (int i = 0; i < 8; i++)
                aq[i] = *(const ulonglong2*)&Xs[buf][my*8 + i][kk];
            #pragma unroll
            for (int j = 0; j < 4; j++)
                wq[j] = *(const ulonglong2*)&Ws[buf][nh*64 + tx + 16*j][kk];
            #pragma unroll
            for (int i = 0; i < 8; i++)
                #pragma unroll
                for (int j = 0; j < 4; j++) {
                    acc2[i][j] = ffma2(aq[i].x, wq[j].x, acc2[i][j]);
                    acc2[i][j] = ffma2(aq[i].y, wq[j].y, acc2[i][j]);
                }
        }
        __syncthreads();
    }

    float bv[4];
    #pragma unroll
    for (int j = 0; j < 4; j++) bv[j] = bias[bn + nh*64 + tx + 16*j];
    #pragma unroll
    for (int i = 0; i < 8; i++) {
        int m = bm + my*8 + i;
        int row = remap ? ((m & (Tq-1)) * Bq + (m >> 9)) : m;
        #pragma unroll
        for (int j = 0; j < 4; j++) {
            float v = u64lo(acc2[i][j]) + u64hi(acc2[i][j]) + bv[j];
            Y[(size_t)row * Gq + bn + nh*64 + tx + 16*j] = v;
        }
    }
}

// ============================================================
// Software grid barrier (all NBLK blocks resident by construction).
// ============================================================
__device__ __forceinline__ void gridbar(unsigned& myphase)
{
    __syncthreads();
    if (threadIdx.x == 0) {
        __threadfence();
        unsigned old = atomicAdd(&g_cnt, 1u);
        if (old == NBLK - 1) {
            g_cnt = 0;
            __threadfence();
            atomicAdd(&g_phase, 1u);
        } else {
            while (*(volatile unsigned*)&g_phase == myphase) { }
            __threadfence();
        }
    }
    __syncthreads();
    myphase++;
}

// ============================================================
// Persistent LSTM layer: 128 blocks x 512 threads, all T steps.
// Block owns 32 gate-cols (8 h-units x 4 gates).
// Whh slice (32x1024 = 128KB) lives in SMEM for the whole layer.
// h streamed per step in 128-k chunks, double-buffered cp.async.
// GEMM: 4-way k-split x (4b x 4n)/thread via FFMA2; all-thread
// smem reduction. c in registers; h ping-pong + gridbar per step.
// ============================================================
__global__ void __launch_bounds__(512, 1)
lstm_layer(const float* __restrict__ xproj, const float* __restrict__ Whh,
           const float* __restrict__ bhh, float* __restrict__ hseq)
{
    extern __shared__ float smem[];
    float* Wsm = smem + WOFF;   // [32][WPAD]
    float* Hsm = smem + HOFF;   // [2][64][HPAD]
    float* Gsm = smem + GOFF;   // [64][36]
    float* Rsm = smem + HOFF;   // partial stash [4][64][36] (unions with Hsm)

    const int tid = threadIdx.x;
    const int bid = blockIdx.x;
    const int j0  = bid * 8;

    unsigned myphase = *(volatile unsigned*)&g_phase;

    // ---- preload weight slice: rows c=0..31 -> (gate=c>>3, jl=c&7)
    #pragma unroll
    for (int l = 0; l < 16; l++) {
        int idx = tid + l * 512;          // 0..8191 float4 slots
        int c  = idx >> 8;                // 256 float4 per row
        int kq = idx & 255;
        int grow = (c >> 3) * Hq + j0 + (c & 7);
        float4 v = *(const float4*)(Whh + (size_t)grow * Hq + kq * 4);
        *(float4*)(Wsm + c * WPAD + kq * 4) = v;
    }

    // GEMM coords: 4-way k-split, tile 4b x 4n
    const int ks  = tid >> 7;     // 0..3 k-quarter of each 128-chunk
    const int pos = tid & 127;
    const int bq  = pos >> 3;     // b = bq + 16i
    const int nq  = pos & 7;      // s = nq + 8j

    // update coords (1 item per thread): b = tid>>3, jl = tid&7
    const int ub = tid >> 3;
    const int ujl = tid & 7;
    float creg = 0.0f;
    float bh[4];
    #pragma unroll
    for (int g2 = 0; g2 < 4; g2++) bh[g2] = bhh[g2 * Hq + j0 + ujl];

    // zero h buffer 0 (this block's 512-float share)
    g_hbuf[0][bid * 512 + tid] = 0.0f;
    gridbar(myphase);

    for (int t = 0; t < Tq; t++) {
        const float* hprev = g_hbuf[t & 1];
        float* hnext = g_hbuf[(t + 1) & 1];

        // prefetch chunk 0 into buf 0 (2048 float4 / 512 thr = 4 each)
        #pragma unroll
        for (int l = 0; l < 4; l++) {
            int idx = tid + l * 512;
            int row = idx >> 5;
            int kq  = idx & 31;
            cp_async16(Hsm + row * HPAD + kq * 4,
                       hprev + (size_t)row * Hq + kq * 4);
        }
        cp_commit();

        // prefetch this step's xproj gate values (hidden behind GEMM)
        float xg[4];
        {
            size_t xb = ((size_t)t * Bq + ub) * Gq + j0 + ujl;
            #pragma unroll
            for (int g2 = 0; g2 < 4; g2++) xg[g2] = xproj[xb + (size_t)g2 * Hq];
        }

        unsigned long long acc2[4][4] = {};
        for (int kc = 0; kc < 8; kc++) {
            const int buf = kc & 1;
            cp_wait0();
            __syncthreads();
            if (kc < 7) {
                float* hdst = Hsm + (buf ^ 1) * HBUF;
                #pragma unroll
                for (int l = 0; l < 4; l++) {
                    int idx = tid + l * 512;
                    int row = idx >> 5;
                    int kq  = idx & 31;
                    cp_async16(hdst + row * HPAD + kq * 4,
                               hprev + (size_t)row * Hq + (kc + 1) * 128 + kq * 4);
                }
                cp_commit();
            }

            const float* hb = Hsm + buf * HBUF + ks * 32;
            const float* wb = Wsm + kc * 128 + ks * 32;
            #pragma unroll
            for (int kk = 0; kk < 32; kk += 4) {
                ulonglong2 hq[4];
                #pragma unroll
                for (int i = 0; i < 4; i++)
                    hq[i] = *(const ulonglong2*)(hb + (bq + 16*i) * HPAD + kk);
                ulonglong2 wq[4];
                #pragma unroll
                for (int j = 0; j < 4; j++)
                    wq[j] = *(const ulonglong2*)(wb + (nq + 8*j) * WPAD + kk);
                #pragma unroll
                for (int i = 0; i < 4; i++)
                    #pragma unroll
                    for (int j = 0; j < 4; j++) {
                        acc2[i][j] = ffma2(hq[i].x, wq[j].x, acc2[i][j]);
                        acc2[i][j] = ffma2(hq[i].y, wq[j].y, acc2[i][j]);
                    }
            }
        }
        __syncthreads();   // compute done; Hsm free for partial stash

        // stash partials: Rsm[ks][b][s], [4][64][36]
        #pragma unroll
        for (int i = 0; i < 4; i++) {
            int b = bq + 16*i;
            float* rp = Rsm + ks * 2304 + b * 36;
            #pragma unroll
            for (int j = 0; j < 4; j++)
                rp[nq + 8*j] = u64lo(acc2[i][j]) + u64hi(acc2[i][j]);
        }
        __syncthreads();

        // all-thread reduction: each thread sums 4 outputs over 4 splits
        {
            int b  = tid >> 3;
            int s0 = (tid & 7) * 4;
            float4 r0 = *(const float4*)(Rsm + 0*2304 + b*36 + s0);
            float4 r1 = *(const float4*)(Rsm + 1*2304 + b*36 + s0);
            float4 r2 = *(const float4*)(Rsm + 2*2304 + b*36 + s0);
            float4 r3 = *(const float4*)(Rsm + 3*2304 + b*36 + s0);
            float4 o;
            o.x = (r0.x + r1.x) + (r2.x + r3.x);
            o.y = (r0.y + r1.y) + (r2.y + r3.y);
            o.z = (r0.z + r1.z) + (r2.z + r3.z);
            o.w = (r0.w + r1.w) + (r2.w + r3.w);
            *(float4*)(Gsm + b*36 + s0) = o;
        }
        __syncthreads();

        // pointwise LSTM update (1 item per thread)
        {
            float gi = Gsm[ub*36 +      ujl] + xg[0] + bh[0];
            float gf = Gsm[ub*36 +  8 + ujl] + xg[1] + bh[1];
            float gg = Gsm[ub*36 + 16 + ujl] + xg[2] + bh[2];
            float go = Gsm[ub*36 + 24 + ujl] + xg[3] + bh[3];
            float ig = 1.0f / (1.0f + expf(-gi));
            float fg = 1.0f / (1.0f + expf(-gf));
            float gv = tanhf(gg);
            float og = 1.0f / (1.0f + expf(-go));
            float cn = fg * creg + ig * gv;
            creg = cn;
            float hn = og * tanhf(cn);
            hnext[(size_t)ub * Hq + j0 + ujl] = hn;
            hseq[((size_t)t * Bq + ub) * Hq + j0 + ujl] = hn;
        }
        gridbar(myphase);
    }
}

// ============================================================
// Emissions: e[(t*B+b), c] = h2_row . fc_w[c] + fc_b[c]; one warp/row.
// ============================================================
__global__ void emis_kernel(const float* __restrict__ h2, const float* __restrict__ fcw,
                            const float* __restrict__ fcb, float* __restrict__ e)
{
    int warp = (blockIdx.x * blockDim.x + threadIdx.x) >> 5;
    int lane = threadIdx.x & 31;
    if (warp >= MTOT) return;
    const float* hr = h2 + (size_t)warp * Hq;
    float acc[Cq];
    #pragma unroll
    for (int cc = 0; cc < Cq; cc++) acc[cc] = 0.0f;
    for (int k = lane; k < Hq; k += 32) {
        float hv = hr[k];
        #pragma unroll
        for (int cc = 0; cc < Cq; cc++)
            acc[cc] = fmaf(hv, fcw[cc*Hq + k], acc[cc]);
    }
    #pragma unroll
    for (int cc = 0; cc < Cq; cc++) {
        float v = acc[cc];
        #pragma unroll
        for (int off = 16; off; off >>= 1) v += __shfl_down_sync(0xffffffffu, v, off);
        if (lane == 0) e[(size_t)warp * Cq + cc] = v + fcb[cc];
    }
}

// ============================================================
// CRF NLL per batch element. One warp per b. emissions in (T,B,C).
// ============================================================
__global__ void crf_kernel(const float* __restrict__ e, const int* __restrict__ labels,
                           const float* __restrict__ startt, const float* __restrict__ endt,
                           const float* __restrict__ trans, float* __restrict__ llh)
{
    int b = blockIdx.x;
    int lane = threadIdx.x;
    const int* lb = labels + (size_t)b * Tq;

    // ---- path score ----
    float part = 0.0f;
    int cnt = 0;
    for (int t = 1 + lane; t < Tq; t += 32) {
        int tag  = lb[t];
        int tagp = lb[t-1];
        if (tag != -1)
            part += trans[tagp*Cq + tag] + e[((size_t)t*Bq + b)*Cq + tag];
    }
    for (int t = lane; t < Tq; t += 32) cnt += (lb[t] != -1);
    #pragma unroll
    for (int off = 16; off; off >>= 1) {
        part += __shfl_down_sync(0xffffffffu, part, off);
        cnt  += __shfl_down_sync(0xffffffffu, cnt, off);
    }
    float score = 0.0f;
    if (lane == 0) {
        int tag0 = lb[0];
        score = startt[tag0] + e[(size_t)b*Cq + tag0] + part;
        int last = cnt - 1;
        score += endt[lb[last]];
    }

    // ---- logZ (forward algorithm) ----
    __shared__ float alpha[Cq];
    float tcol[Cq];
    if (lane < Cq) {
        #pragma unroll
        for (int cc = 0; cc < Cq; cc++) tcol[cc] = trans[cc*Cq + lane];
        alpha[lane] = startt[lane] + e[(size_t)b*Cq + lane];
    }
    __syncwarp();
    for (int t = 1; t < Tq; t++) {
        bool m = (lb[t] != -1);
        float av[Cq];
        #pragma unroll
        for (int cc = 0; cc < Cq; cc++) av[cc] = alpha[cc];
        float nxt = 0.0f;
        if (lane < Cq) {
            float mx = -1e30f;
            #pragma unroll
            for (int cc = 0; cc < Cq; cc++) mx = fmaxf(mx, av[cc] + tcol[cc]);
            float s = 0.0f;
            #pragma unroll
            for (int cc = 0; cc < Cq; cc++) s += expf(av[cc] + tcol[cc] - mx);
            nxt = mx + logf(s) + e[((size_t)t*Bq + b)*Cq + lane];
        }
        __syncwarp();
        if (m && lane < Cq) alpha[lane] = nxt;
        __syncwarp();
    }
    float v = (lane < Cq) ? alpha[lane] + endt[lane] : -1e30f;
    float mx = v;
    #pragma unroll
    for (int off = 16; off; off >>= 1) mx = fmaxf(mx, __shfl_xor_sync(0xffffffffu, mx, off));
    float sv = (lane < Cq) ? expf(v - mx) : 0.0f;
    #pragma unroll
    for (int off = 16; off; off >>= 1) sv += __shfl_xor_sync(0xffffffffu, sv, off);
    if (lane == 0) llh[b] = score - (mx + logf(sv));
}

__global__ void finalize_kernel(const float* __restrict__ llh, float* __restrict__ out)
{
    __shared__ float s[64];
    int lane = threadIdx.x;
    s[lane] = llh[lane];
    __syncthreads();
    #pragma unroll
    for (int off = 32; off; off >>= 1) {
        if (lane < off) s[lane] += s[lane + off];
        __syncthreads();
    }
    if (lane == 0) out[0] = -s[0] / (float)Bq;
}

// ============================================================
extern "C" void kernel_launch(void* const* d_in, const int* in_sizes, int n_in,
                              void* d_out, int out_size)
{
    const float* x     = (const float*)d_in[0];
    const int*   labels= (const int*)  d_in[1];
    // d_in[2] = lengths (unused; reference derives mask from labels)
    const float* Wih0  = (const float*)d_in[3];
    const float* Whh0  = (const float*)d_in[4];
    const float* bih0  = (const float*)d_in[5];
    const float* bhh0  = (const float*)d_in[6];
    const float* Wih1  = (const float*)d_in[7];
    const float* Whh1  = (const float*)d_in[8];
    const float* bih1  = (const float*)d_in[9];
    const float* bhh1  = (const float*)d_in[10];
    const float* fcw   = (const float*)d_in[11];
    const float* fcb   = (const float*)d_in[12];
    const float* startt= (const float*)d_in[13];
    const float* endt  = (const float*)d_in[14];
    const float* trans = (const float*)d_in[15];

    float *xproj, *hseq1, *hseq2, *emis, *llh;
    cudaGetSymbolAddress((void**)&xproj, g_xproj);
    cudaGetSymbolAddress((void**)&hseq1, g_hseq1);
    cudaGetSymbolAddress((void**)&hseq2, g_hseq2);
    cudaGetSymbolAddress((void**)&emis,  g_emis);
    cudaGetSymbolAddress((void**)&llh,   g_llh);

    cudaFuncSetAttribute(lstm_layer, cudaFuncAttributeMaxDynamicSharedMemorySize, SMEM_BYTES);

    dim3 gsX(Gq/128, MTOT/128);      // (32, 256)

    // ---- layer 1 ----
    sgemm128<<<gsX, 512>>>(x, Wih0, bih0, xproj, Iq, /*remap=*/1);
    lstm_layer<<<NBLK, 512, SMEM_BYTES>>>(xproj, Whh0, bhh0, hseq1);

    // ---- layer 2 ----
    sgemm128<<<gsX, 512>>>(hseq1, Wih1, bih1, xproj, Hq, /*remap=*/0);
    lstm_layer<<<NBLK, 512, SMEM_BYTES>>>(xproj, Whh1, bhh1, hseq2);

    // ---- emissions + CRF ----
    emis_kernel<<<(MTOT*32)/256, 256>>>(hseq2, fcw, fcb, emis);
    crf_kernel<<<Bq, 32>>>(emis, labels, startt, endt, trans, llh);
    finalize_kernel<<<1, 64>>>(llh, (float*)d_out);
}

// round 8
// speedup vs baseline: 1.3150x; 1.3150x over previous
#include <cuda_runtime.h>
#include <math.h>
#include <stdint.h>

// Problem constants
#define Bq 64
#define Tq 512
#define Iq 512
#define Hq 1024
#define Gq 4096      // 4*H
#define Cq 20
#define MTOT (Bq*Tq) // 32768
#define NBLK 128     // persistent blocks (<148 => all co-resident)

// lstm_layer shared-memory layout (floats)
#define WPAD 1028                 // 1024 + 4
#define HPAD 132                  // 128 + 4
#define HBUF (64*HPAD)            // one h chunk buffer: 8448 floats
#define WOFF 0                    // weights: 32 x WPAD = 32896
#define HOFF (32*WPAD)            // h double buffer: 2*HBUF = 16896
#define GOFF (HOFF + 2*HBUF)      // gate tile: 64 x 36 = 2304
#define SMEM_FLOATS (GOFF + 64*36)
#define SMEM_BYTES (SMEM_FLOATS * 4)

// sgemm_tf32 smem: Xs[2][128][20] + Ws[2][256][20]
#define GEMM_SMEM_FLOATS (2*128*20 + 2*256*20)
#define GEMM_SMEM_BYTES (GEMM_SMEM_FLOATS * 4)   // 61440

// ---- scratch (static device allocations; no cudaMalloc allowed) ----
__device__ float g_xproj[(size_t)MTOT * Gq];   // 512 MB, reused by both layers
__device__ float g_hseq1[(size_t)MTOT * Hq];   // 134 MB (T,B,H)
__device__ float g_hseq2[(size_t)MTOT * Hq];   // 134 MB (T,B,H)
__device__ float g_xt[(size_t)MTOT * Hq];      // 128 MB tf32-rounded activations
__device__ float g_wt[(size_t)Gq * Hq];        // 16 MB tf32-rounded weights
__device__ float g_hbuf[2][Bq * Hq];           // h ping-pong
__device__ float g_emis[(size_t)MTOT * Cq];    // (T,B,C)
__device__ float g_llh[Bq];
__device__ unsigned g_cnt;
__device__ unsigned g_phase;

// ---- packed f32x2 helpers (FFMA2: 2x fp32 FMA per instruction) ----
__device__ __forceinline__ unsigned long long ffma2(unsigned long long a,
                                                    unsigned long long b,
                                                    unsigned long long c)
{
    unsigned long long d;
    asm("fma.rn.f32x2 %0, %1, %2, %3;" : "=l"(d) : "l"(a), "l"(b), "l"(c));
    return d;
}
__device__ __forceinline__ float u64lo(unsigned long long v)
{
    return __uint_as_float((unsigned)(v & 0xffffffffull));
}
__device__ __forceinline__ float u64hi(unsigned long long v)
{
    return __uint_as_float((unsigned)(v >> 32));
}

__device__ __forceinline__ void cp_async16(void* smem_dst, const void* gmem_src)
{
    uint32_t s = (uint32_t)__cvta_generic_to_shared(smem_dst);
    asm volatile("cp.async.cg.shared.global [%0], [%1], 16;\n" :: "r"(s), "l"(gmem_src));
}
__device__ __forceinline__ void cp_commit()
{
    asm volatile("cp.async.commit_group;\n");
}
__device__ __forceinline__ void cp_wait0()
{
    asm volatile("cp.async.wait_group 0;\n");
}

// tf32 MMA: D(16x8) += A(16x8,row) * B(8x8,col)
__device__ __forceinline__ void mma_tf32(float* d, const uint32_t* a, const uint32_t* b)
{
    asm volatile(
        "mma.sync.aligned.m16n8k8.row.col.f32.tf32.tf32.f32 "
        "{%0,%1,%2,%3}, {%4,%5,%6,%7}, {%8,%9}, {%0,%1,%2,%3};"
        : "+f"(d[0]), "+f"(d[1]), "+f"(d[2]), "+f"(d[3])
        : "r"(a[0]), "r"(a[1]), "r"(a[2]), "r"(a[3]), "r"(b[0]), "r"(b[1]));
}

// ============================================================
// Elementwise fp32 -> tf32-rounded fp32 (cvt.rna).
// ============================================================
__global__ void cvt_tf32(const float* __restrict__ src, float* __restrict__ dst, int nquads)
{
    int i = blockIdx.x * blockDim.x + threadIdx.x;
    if (i >= nquads) return;
    float4 v = *(const float4*)(src + (size_t)i * 4);
    uint32_t o0, o1, o2, o3;
    asm("cvt.rna.tf32.f32 %0, %1;" : "=r"(o0) : "f"(v.x));
    asm("cvt.rna.tf32.f32 %0, %1;" : "=r"(o1) : "f"(v.y));
    asm("cvt.rna.tf32.f32 %0, %1;" : "=r"(o2) : "f"(v.z));
    asm("cvt.rna.tf32.f32 %0, %1;" : "=r"(o3) : "f"(v.w));
    float4 o;
    o.x = __uint_as_float(o0); o.y = __uint_as_float(o1);
    o.z = __uint_as_float(o2); o.w = __uint_as_float(o3);
    *(float4*)(dst + (size_t)i * 4) = o;
}

// ============================================================
// tf32 tensor-core GEMM: Y = X(MxK)*W(NxK)^T + bias
// Block tile 128m x 256n, BK=16, 512 threads (16 warps),
// warp tile 32m x 64n (2 m16-tiles x 8 n8-tiles).
// X, W must be tf32-pre-rounded. cp.async double-buffered.
// If remap!=0, X row m = b*T+t and output row becomes t*B+b.
// ============================================================
__global__ void __launch_bounds__(512, 1)
sgemm_tf32(const float* __restrict__ X, const float* __restrict__ W,
           const float* __restrict__ bias, float* __restrict__ Y,
           int K, int remap)
{
    extern __shared__ float gsm[];
    // Xs[2][128][20], Ws[2][256][20]
    float* Xs = gsm;
    float* Ws = gsm + 2 * 128 * 20;
    const uint32_t* Xu = (const uint32_t*)Xs;
    const uint32_t* Wu = (const uint32_t*)Ws;

    const int bn = blockIdx.x * 256;
    const int bm = blockIdx.y * 128;
    const int tid = threadIdx.x;
    const int warp = tid >> 5;
    const int lane = tid & 31;
    const int gid = lane >> 2;       // 0..7
    const int tg  = lane & 3;        // 0..3
    const int wm = warp >> 2;        // m block: wm*32
    const int wn = warp & 3;         // n block: wn*64

    // tile-load coords
    const int xr = tid >> 2;         // 0..127 (X row)
    const int xk = (tid & 3) * 4;

    float acc[2][8][4] = {};

    // prefetch tile 0
    cp_async16(&Xs[0*128*20 + xr*20 + xk], X + (size_t)(bm + xr) * K + xk);
    #pragma unroll
    for (int l = 0; l < 2; l++) {
        int idx = tid + l * 512;
        int r = idx >> 2;
        int kk = (idx & 3) * 4;
        cp_async16(&Ws[0*256*20 + r*20 + kk], W + (size_t)(bn + r) * K + kk);
    }
    cp_commit();

    const int nb = K >> 4;
    for (int kb = 0; kb < nb; kb++) {
        const int buf = kb & 1;
        cp_wait0();
        __syncthreads();
        if (kb + 1 < nb) {
            int k0 = (kb + 1) << 4;
            cp_async16(&Xs[(buf^1)*128*20 + xr*20 + xk], X + (size_t)(bm + xr) * K + k0 + xk);
            #pragma unroll
            for (int l = 0; l < 2; l++) {
                int idx = tid + l * 512;
                int r = idx >> 2;
                int kk = (idx & 3) * 4;
                cp_async16(&Ws[(buf^1)*256*20 + r*20 + kk], W + (size_t)(bn + r) * K + k0 + kk);
            }
            cp_commit();
        }

        const uint32_t* xb = Xu + buf * 128 * 20;
        const uint32_t* wb = Wu + buf * 256 * 20;
        #pragma unroll
        for (int k8 = 0; k8 < 16; k8 += 8) {
            uint32_t afr[2][4];
            #pragma unroll
            for (int mt = 0; mt < 2; mt++) {
                int r0 = wm*32 + mt*16 + gid;
                afr[mt][0] = xb[r0*20 + k8 + tg];
                afr[mt][1] = xb[(r0+8)*20 + k8 + tg];
                afr[mt][2] = xb[r0*20 + k8 + tg + 4];
                afr[mt][3] = xb[(r0+8)*20 + k8 + tg + 4];
            }
            uint32_t bfr[8][2];
            #pragma unroll
            for (int nt = 0; nt < 8; nt++) {
                int nr = wn*64 + nt*8 + gid;
                bfr[nt][0] = wb[nr*20 + k8 + tg];
                bfr[nt][1] = wb[nr*20 + k8 + tg + 4];
            }
            #pragma unroll
            for (int mt = 0; mt < 2; mt++)
                #pragma unroll
                for (int nt = 0; nt < 8; nt++)
                    mma_tf32(acc[mt][nt], afr[mt], bfr[nt]);
        }
        __syncthreads();
    }

    // epilogue
    #pragma unroll
    for (int mt = 0; mt < 2; mt++) {
        int m0 = bm + wm*32 + mt*16 + gid;
        int row0 = remap ? ((m0 & (Tq-1)) * Bq + (m0 >> 9)) : m0;
        int m1 = m0 + 8;
        int row1 = remap ? ((m1 & (Tq-1)) * Bq + (m1 >> 9)) : m1;
        #pragma unroll
        for (int nt = 0; nt < 8; nt++) {
            int c0 = bn + wn*64 + nt*8 + tg*2;
            float2 bv = *(const float2*)(bias + c0);
            float2 o0, o1;
            o0.x = acc[mt][nt][0] + bv.x; o0.y = acc[mt][nt][1] + bv.y;
            o1.x = acc[mt][nt][2] + bv.x; o1.y = acc[mt][nt][3] + bv.y;
            *(float2*)(Y + (size_t)row0 * Gq + c0) = o0;
            *(float2*)(Y + (size_t)row1 * Gq + c0) = o1;
        }
    }
}

// ============================================================
// Software grid barrier (all NBLK blocks resident by construction).
// ============================================================
__device__ __forceinline__ void gridbar(unsigned& myphase)
{
    __syncthreads();
    if (threadIdx.x == 0) {
        __threadfence();
        unsigned old = atomicAdd(&g_cnt, 1u);
        if (old == NBLK - 1) {
            g_cnt = 0;
            __threadfence();
            atomicAdd(&g_phase, 1u);
        } else {
            while (*(volatile unsigned*)&g_phase == myphase) { }
            __threadfence();
        }
    }
    __syncthreads();
    myphase++;
}

// ============================================================
// Persistent LSTM layer (best-measured R6 config): 128 blocks x
// 256 threads, Whh slice in SMEM, FFMA2 GEMM, c in registers.
// ============================================================
__global__ void __launch_bounds__(256, 1)
lstm_layer(const float* __restrict__ xproj, const float* __restrict__ Whh,
           const float* __restrict__ bhh, float* __restrict__ hseq)
{
    extern __shared__ float smem[];
    float* Wsm = smem + WOFF;   // [32][WPAD]
    float* Hsm = smem + HOFF;   // [2][64][HPAD]
    float* Gsm = smem + GOFF;   // [64][36]
    float* Rsm = smem + HOFF;   // reduction scratch (unions with Hsm)

    const int tid = threadIdx.x;
    const int bid = blockIdx.x;
    const int j0  = bid * 8;

    unsigned myphase = *(volatile unsigned*)&g_phase;

    // ---- preload weight slice into smem: rows c=0..31 -> (gate=c>>3, jl=c&7)
    #pragma unroll
    for (int l = 0; l < 32; l++) {
        int idx = tid + l * 256;          // 0..8191 float4 slots
        int c  = idx >> 8;                // 256 float4 per row
        int kq = idx & 255;
        int grow = (c >> 3) * Hq + j0 + (c & 7);
        float4 v = *(const float4*)(Whh + (size_t)grow * Hq + kq * 4);
        *(float4*)(Wsm + c * WPAD + kq * 4) = v;
    }

    // GEMM coords
    const int ks  = tid >> 6;     // 0..3 k-split
    const int pos = tid & 63;
    const int bq  = pos >> 3;     // b = bq + 8i
    const int nq  = pos & 7;      // n = nq + 8j

    // update coords (2 items per thread)
    float creg[2] = {0.0f, 0.0f};
    float bh[2][4];
    #pragma unroll
    for (int q = 0; q < 2; q++) {
        int p = tid + q * 256;
        int jl = p & 7;
        #pragma unroll
        for (int g2 = 0; g2 < 4; g2++) bh[q][g2] = bhh[g2 * Hq + j0 + jl];
    }

    // zero h buffer 0
    {
        int idx = bid * 512 + tid;
        g_hbuf[0][idx] = 0.0f;
        g_hbuf[0][idx + 256] = 0.0f;
    }
    gridbar(myphase);

    for (int t = 0; t < Tq; t++) {
        const float* hprev = g_hbuf[t & 1];
        float* hnext = g_hbuf[(t + 1) & 1];

        // prefetch chunk 0 into buf 0
        #pragma unroll
        for (int l = 0; l < 8; l++) {
            int idx = tid + l * 256;      // 2048 float4
            int row = idx >> 5;
            int kq  = idx & 31;
            cp_async16(Hsm + row * HPAD + kq * 4,
                       hprev + (size_t)row * Hq + kq * 4);
        }
        cp_commit();

        // prefetch this step's xproj gate values (hidden behind GEMM)
        float xg[2][4];
        #pragma unroll
        for (int q = 0; q < 2; q++) {
            int p = tid + q * 256;
            int b = p >> 3, jl = p & 7;
            size_t xb = ((size_t)t * Bq + b) * Gq + j0 + jl;
            #pragma unroll
            for (int g2 = 0; g2 < 4; g2++) xg[q][g2] = xproj[xb + (size_t)g2 * Hq];
        }

        unsigned long long acc2[8][4] = {};
        for (int kc = 0; kc < 8; kc++) {
            const int buf = kc & 1;
            cp_wait0();
            __syncthreads();
            if (kc < 7) {
                float* hdst = Hsm + (buf ^ 1) * HBUF;
                #pragma unroll
                for (int l = 0; l < 8; l++) {
                    int idx = tid + l * 256;
                    int row = idx >> 5;
                    int kq  = idx & 31;
                    cp_async16(hdst + row * HPAD + kq * 4,
                               hprev + (size_t)row * Hq + (kc + 1) * 128 + kq * 4);
                }
                cp_commit();
            }

            const float* hb = Hsm + buf * HBUF + ks * 32;
            const float* wb = Wsm + kc * 128 + ks * 32;
            #pragma unroll
            for (int kk = 0; kk < 32; kk += 4) {
                ulonglong2 hq[8];
                #pragma unroll
                for (int i = 0; i < 8; i++)
                    hq[i] = *(const ulonglong2*)(hb + (bq + 8*i) * HPAD + kk);
                ulonglong2 wq[4];
                #pragma unroll
                for (int j = 0; j < 4; j++)
                    wq[j] = *(const ulonglong2*)(wb + (nq + 8*j) * WPAD + kk);
                #pragma unroll
                for (int i = 0; i < 8; i++)
                    #pragma unroll
                    for (int j = 0; j < 4; j++) {
                        acc2[i][j] = ffma2(hq[i].x, wq[j].x, acc2[i][j]);
                        acc2[i][j] = ffma2(hq[i].y, wq[j].y, acc2[i][j]);
                    }
            }
        }
        __syncthreads();   // all compute done; Hsm free for reduction

        // unpack even/odd-k partial sums
        float acc[8][4];
        #pragma unroll
        for (int i = 0; i < 8; i++)
            #pragma unroll
            for (int j = 0; j < 4; j++)
                acc[i][j] = u64lo(acc2[i][j]) + u64hi(acc2[i][j]);

        // k-split reduction through smem
        if (ks > 0) {
            float* rp = Rsm + ((ks - 1) * 64 + pos) * 36;
            #pragma unroll
            for (int i = 0; i < 8; i++)
                *(float4*)(rp + i * 4) = *(float4*)acc[i];
        }
        __syncthreads();
        if (ks == 0) {
            #pragma unroll
            for (int s = 0; s < 3; s++) {
                const float* rp = Rsm + (s * 64 + pos) * 36;
                #pragma unroll
                for (int i = 0; i < 8; i++) {
                    float4 v = *(const float4*)(rp + i * 4);
                    acc[i][0] += v.x; acc[i][1] += v.y;
                    acc[i][2] += v.z; acc[i][3] += v.w;
                }
            }
            #pragma unroll
            for (int i = 0; i < 8; i++) {
                int b = bq + 8*i;
                #pragma unroll
                for (int j = 0; j < 4; j++)
                    Gsm[b * 36 + nq + 8*j] = acc[i][j];
            }
        }
        __syncthreads();

        // pointwise LSTM update
        #pragma unroll
        for (int q = 0; q < 2; q++) {
            int p = tid + q * 256;
            int b = p >> 3, jl = p & 7;
            float gi = Gsm[b*36 +      jl] + xg[q][0] + bh[q][0];
            float gf = Gsm[b*36 +  8 + jl] + xg[q][1] + bh[q][1];
            float gg = Gsm[b*36 + 16 + jl] + xg[q][2] + bh[q][2];
            float go = Gsm[b*36 + 24 + jl] + xg[q][3] + bh[q][3];
            float ig = 1.0f / (1.0f + expf(-gi));
            float fg = 1.0f / (1.0f + expf(-gf));
            float gv = tanhf(gg);
            float og = 1.0f / (1.0f + expf(-go));
            float cn = fg * creg[q] + ig * gv;
            creg[q] = cn;
            float hn = og * tanhf(cn);
            hnext[(size_t)b * Hq + j0 + jl] = hn;
            hseq[((size_t)t * Bq + b) * Hq + j0 + jl] = hn;
        }
        gridbar(myphase);
    }
}

// ============================================================
// Emissions: e[(t*B+b), c] = h2_row . fc_w[c] + fc_b[c]; one warp/row.
// ============================================================
__global__ void emis_kernel(const float* __restrict__ h2, const float* __restrict__ fcw,
                            const float* __restrict__ fcb, float* __restrict__ e)
{
    int warp = (blockIdx.x * blockDim.x + threadIdx.x) >> 5;
    int lane = threadIdx.x & 31;
    if (warp >= MTOT) return;
    const float* hr = h2 + (size_t)warp * Hq;
    float acc[Cq];
    #pragma unroll
    for (int cc = 0; cc < Cq; cc++) acc[cc] = 0.0f;
    for (int k = lane; k < Hq; k += 32) {
        float hv = hr[k];
        #pragma unroll
        for (int cc = 0; cc < Cq; cc++)
            acc[cc] = fmaf(hv, fcw[cc*Hq + k], acc[cc]);
    }
    #pragma unroll
    for (int cc = 0; cc < Cq; cc++) {
        float v = acc[cc];
        #pragma unroll
        for (int off = 16; off; off >>= 1) v += __shfl_down_sync(0xffffffffu, v, off);
        if (lane == 0) e[(size_t)warp * Cq + cc] = v + fcb[cc];
    }
}

// ============================================================
// CRF NLL per batch element. One warp per b. emissions in (T,B,C).
// ============================================================
__global__ void crf_kernel(const float* __restrict__ e, const int* __restrict__ labels,
                           const float* __restrict__ startt, const float* __restrict__ endt,
                           const float* __restrict__ trans, float* __restrict__ llh)
{
    int b = blockIdx.x;
    int lane = threadIdx.x;
    const int* lb = labels + (size_t)b * Tq;

    // ---- path score ----
    float part = 0.0f;
    int cnt = 0;
    for (int t = 1 + lane; t < Tq; t += 32) {
        int tag  = lb[t];
        int tagp = lb[t-1];
        if (tag != -1)
            part += trans[tagp*Cq + tag] + e[((size_t)t*Bq + b)*Cq + tag];
    }
    for (int t = lane; t < Tq; t += 32) cnt += (lb[t] != -1);
    #pragma unroll
    for (int off = 16; off; off >>= 1) {
        part += __shfl_down_sync(0xffffffffu, part, off);
        cnt  += __shfl_down_sync(0xffffffffu, cnt, off);
    }
    float score = 0.0f;
    if (lane == 0) {
        int tag0 = lb[0];
        score = startt[tag0] + e[(size_t)b*Cq + tag0] + part;
        int last = cnt - 1;
        score += endt[lb[last]];
    }

    // ---- logZ (forward algorithm) ----
    __shared__ float alpha[Cq];
    float tcol[Cq];
    if (lane < Cq) {
        #pragma unroll
        for (int cc = 0; cc < Cq; cc++) tcol[cc] = trans[cc*Cq + lane];
        alpha[lane] = startt[lane] + e[(size_t)b*Cq + lane];
    }
    __syncwarp();
    for (int t = 1; t < Tq; t++) {
        bool m = (lb[t] != -1);
        float av[Cq];
        #pragma unroll
        for (int cc = 0; cc < Cq; cc++) av[cc] = alpha[cc];
        float nxt = 0.0f;
        if (lane < Cq) {
            float mx = -1e30f;
            #pragma unroll
            for (int cc = 0; cc < Cq; cc++) mx = fmaxf(mx, av[cc] + tcol[cc]);
            float s = 0.0f;
            #pragma unroll
            for (int cc = 0; cc < Cq; cc++) s += expf(av[cc] + tcol[cc] - mx);
            nxt = mx + logf(s) + e[((size_t)t*Bq + b)*Cq + lane];
        }
        __syncwarp();
        if (m && lane < Cq) alpha[lane] = nxt;
        __syncwarp();
    }
    float v = (lane < Cq) ? alpha[lane] + endt[lane] : -1e30f;
    float mx = v;
    #pragma unroll
    for (int off = 16; off; off >>= 1) mx = fmaxf(mx, __shfl_xor_sync(0xffffffffu, mx, off));
    float sv = (lane < Cq) ? expf(v - mx) : 0.0f;
    #pragma unroll
    for (int off = 16; off; off >>= 1) sv += __shfl_xor_sync(0xffffffffu, sv, off);
    if (lane == 0) llh[b] = score - (mx + logf(sv));
}

__global__ void finalize_kernel(const float* __restrict__ llh, float* __restrict__ out)
{
    __shared__ float s[64];
    int lane = threadIdx.x;
    s[lane] = llh[lane];
    __syncthreads();
    #pragma unroll
    for (int off = 32; off; off >>= 1) {
        if (lane < off) s[lane] += s[lane + off];
        __syncthreads();
    }
    if (lane == 0) out[0] = -s[0] / (float)Bq;
}

// ============================================================
extern "C" void kernel_launch(void* const* d_in, const int* in_sizes, int n_in,
                              void* d_out, int out_size)
{
    const float* x     = (const float*)d_in[0];
    const int*   labels= (const int*)  d_in[1];
    // d_in[2] = lengths (unused; reference derives mask from labels)
    const float* Wih0  = (const float*)d_in[3];
    const float* Whh0  = (const float*)d_in[4];
    const float* bih0  = (const float*)d_in[5];
    const float* bhh0  = (const float*)d_in[6];
    const float* Wih1  = (const float*)d_in[7];
    const float* Whh1  = (const float*)d_in[8];
    const float* bih1  = (const float*)d_in[9];
    const float* bhh1  = (const float*)d_in[10];
    const float* fcw   = (const float*)d_in[11];
    const float* fcb   = (const float*)d_in[12];
    const float* startt= (const float*)d_in[13];
    const float* endt  = (const float*)d_in[14];
    const float* trans = (const float*)d_in[15];

    float *xproj, *hseq1, *hseq2, *xt, *wt, *emis, *llh;
    cudaGetSymbolAddress((void**)&xproj, g_xproj);
    cudaGetSymbolAddress((void**)&hseq1, g_hseq1);
    cudaGetSymbolAddress((void**)&hseq2, g_hseq2);
    cudaGetSymbolAddress((void**)&xt,    g_xt);
    cudaGetSymbolAddress((void**)&wt,    g_wt);
    cudaGetSymbolAddress((void**)&emis,  g_emis);
    cudaGetSymbolAddress((void**)&llh,   g_llh);

    cudaFuncSetAttribute(lstm_layer, cudaFuncAttributeMaxDynamicSharedMemorySize, SMEM_BYTES);
    cudaFuncSetAttribute(sgemm_tf32, cudaFuncAttributeMaxDynamicSharedMemorySize, GEMM_SMEM_BYTES);

    dim3 gsX(Gq/256, MTOT/128);      // (16, 256)

    // ---- layer 1 ----
    cvt_tf32<<<(MTOT*Iq/4 + 255)/256, 256>>>(x, xt, MTOT*Iq/4);
    cvt_tf32<<<(Gq*Iq/4 + 255)/256, 256>>>(Wih0, wt, Gq*Iq/4);
    sgemm_tf32<<<gsX, 512, GEMM_SMEM_BYTES>>>(xt, wt, bih0, xproj, Iq, /*remap=*/1);
    lstm_layer<<<NBLK, 256, SMEM_BYTES>>>(xproj, Whh0, bhh0, hseq1);

    // ---- layer 2 ----
    cvt_tf32<<<(MTOT*Hq/4 + 255)/256, 256>>>(hseq1, xt, MTOT*Hq/4);
    cvt_tf32<<<(Gq*Hq/4 + 255)/256, 256>>>(Wih1, wt, Gq*Hq/4);
    sgemm_tf32<<<gsX, 512, GEMM_SMEM_BYTES>>>(xt, wt, bih1, xproj, Hq, /*remap=*/0);
    lstm_layer<<<NBLK, 256, SMEM_BYTES>>>(xproj, Whh1, bhh1, hseq2);

    // ---- emissions + CRF ----
    emis_kernel<<<(MTOT*32)/256, 256>>>(hseq2, fcw, fcb, emis);
    crf_kernel<<<Bq, 32>>>(emis, labels, startt, endt, trans, llh);
    finalize_kernel<<<1, 64>>>(llh, (float*)d_out);
}

// round 10
// speedup vs baseline: 1.4687x; 1.1169x over previous
#include <cuda_runtime.h>
#include <cuda_bf16.h>
#include <math.h>
#include <stdint.h>

// Problem constants
#define Bq 64
#define Tq 512
#define Iq 512
#define Hq 1024
#define Gq 4096      // 4*H
#define Cq 20
#define MTOT (Bq*Tq) // 32768
#define NBLK 128     // persistent blocks (<148 => all co-resident)

// lstm_layer shared-memory layout (floats)
#define WPAD 1028                 // 1024 + 4
#define HPAD 132                  // 128 + 4
#define HBUF (64*HPAD)            // one h chunk buffer: 8448 floats
#define WOFF 0                    // weights: 32 x WPAD = 32896
#define HOFF (32*WPAD)            // h double buffer: 2*HBUF = 16896
#define GOFF (HOFF + 2*HBUF)      // gate tile: 64 x 36 = 2304
#define SMEM_FLOATS (GOFF + 64*36)
#define SMEM_BYTES (SMEM_FLOATS * 4)

// sgemm_bf16 smem (uint32 words): Xs[2][128][20] + Ws[2][256][20]
// Row stride 20 words = 80 bytes: 16-byte aligned (cp.async requirement)
// and fragment LDS bank-conflict-free (20*gid mod 32 all-distinct).
#define GRS 20
#define GEMM_SMEM_WORDS (2*128*GRS + 2*256*GRS)
#define GEMM_SMEM_BYTES (GEMM_SMEM_WORDS * 4)    // 61440

// ---- scratch (static device allocations; no cudaMalloc allowed) ----
__device__ float g_xproj[(size_t)MTOT * Gq];   // 512 MB, reused by both layers
__device__ float g_hseq1[(size_t)MTOT * Hq];   // 134 MB (T,B,H)
__device__ float g_hseq2[(size_t)MTOT * Hq];   // 134 MB (T,B,H)
__device__ __nv_bfloat16 g_xb[(size_t)MTOT * Hq];  // 64 MB bf16 activations
__device__ __nv_bfloat16 g_wb[(size_t)Gq * Hq];    // 8 MB bf16 weights
__device__ float g_hbuf[2][Bq * Hq];           // h ping-pong
__device__ float g_emis[(size_t)MTOT * Cq];    // (T,B,C)
__device__ float g_llh[Bq];
__device__ unsigned g_cnt;
__device__ unsigned g_phase;

// ---- packed f32x2 helpers (FFMA2: 2x fp32 FMA per instruction) ----
__device__ __forceinline__ unsigned long long ffma2(unsigned long long a,
                                                    unsigned long long b,
                                                    unsigned long long c)
{
    unsigned long long d;
    asm("fma.rn.f32x2 %0, %1, %2, %3;" : "=l"(d) : "l"(a), "l"(b), "l"(c));
    return d;
}
__device__ __forceinline__ float u64lo(unsigned long long v)
{
    return __uint_as_float((unsigned)(v & 0xffffffffull));
}
__device__ __forceinline__ float u64hi(unsigned long long v)
{
    return __uint_as_float((unsigned)(v >> 32));
}

__device__ __forceinline__ void cp_async16(void* smem_dst, const void* gmem_src)
{
    uint32_t s = (uint32_t)__cvta_generic_to_shared(smem_dst);
    asm volatile("cp.async.cg.shared.global [%0], [%1], 16;\n" :: "r"(s), "l"(gmem_src));
}
__device__ __forceinline__ void cp_commit()
{
    asm volatile("cp.async.commit_group;\n");
}
__device__ __forceinline__ void cp_wait0()
{
    asm volatile("cp.async.wait_group 0;\n");
}

// bf16 MMA: D(16x8,f32) += A(16x16,row,bf16) * B(16x8,col,bf16)
__device__ __forceinline__ void mma_bf16(float* d, const uint32_t* a, const uint32_t* b)
{
    asm volatile(
        "mma.sync.aligned.m16n8k16.row.col.f32.bf16.bf16.f32 "
        "{%0,%1,%2,%3}, {%4,%5,%6,%7}, {%8,%9}, {%0,%1,%2,%3};"
        : "+f"(d[0]), "+f"(d[1]), "+f"(d[2]), "+f"(d[3])
        : "r"(a[0]), "r"(a[1]), "r"(a[2]), "r"(a[3]), "r"(b[0]), "r"(b[1]));
}

// ============================================================
// Elementwise fp32 -> bf16.
// ============================================================
__global__ void cvt_bf16(const float* __restrict__ src, __nv_bfloat16* __restrict__ dst,
                         int nquads)
{
    int i = blockIdx.x * blockDim.x + threadIdx.x;
    if (i >= nquads) return;
    float4 v = *(const float4*)(src + (size_t)i * 4);
    __nv_bfloat162 p0 = __floats2bfloat162_rn(v.x, v.y);
    __nv_bfloat162 p1 = __floats2bfloat162_rn(v.z, v.w);
    uint2 o;
    o.x = *(const uint32_t*)&p0;
    o.y = *(const uint32_t*)&p1;
    *(uint2*)(dst + (size_t)i * 4) = o;
}

// ============================================================
// bf16 tensor-core GEMM: Y = X(MxK)*W(NxK)^T + bias (fp32 out)
// Block tile 128m x 256n, BK=32, 512 threads (16 warps),
// warp tile 32m x 64n (2 m16-tiles x 8 n8-tiles), m16n8k16.
// X, W bf16. cp.async double-buffered, word-stride-20 smem rows.
// If remap!=0, X row m = b*T+t and output row becomes t*B+b.
// ============================================================
__global__ void __launch_bounds__(512)
sgemm_bf16(const __nv_bfloat16* __restrict__ X, const __nv_bfloat16* __restrict__ W,
           const float* __restrict__ bias, float* __restrict__ Y,
           int K, int remap)
{
    extern __shared__ uint32_t gsm[];
    uint32_t* Xs = gsm;                 // [2][128][GRS]
    uint32_t* Ws = gsm + 2 * 128 * GRS; // [2][256][GRS]

    const int bn = blockIdx.x * 256;
    const int bm = blockIdx.y * 128;
    const int tid = threadIdx.x;
    const int warp = tid >> 5;
    const int lane = tid & 31;
    const int gid = lane >> 2;       // 0..7
    const int tg  = lane & 3;        // 0..3
    const int wm = warp >> 2;        // m block: wm*32
    const int wn = warp & 3;         // n block: wn*64

    // tile-load coords: 8 bf16 (16B) per cp.async
    const int lr = tid >> 2;         // X row 0..127 / W row base
    const int ls = (tid & 3);        // segment 0..3 (8 bf16 each)

    float acc[2][8][4] = {};

    // prefetch tile 0
    cp_async16(&Xs[0*128*GRS + lr*GRS + ls*4], X + (size_t)(bm + lr) * K + ls*8);
    #pragma unroll
    for (int l = 0; l < 2; l++) {
        int idx = tid + l * 512;
        int r = idx >> 2;
        int s = idx & 3;
        cp_async16(&Ws[0*256*GRS + r*GRS + s*4], W + (size_t)(bn + r) * K + s*8);
    }
    cp_commit();

    const int nb = K >> 5;
    for (int kb = 0; kb < nb; kb++) {
        const int buf = kb & 1;
        cp_wait0();
        __syncthreads();
        if (kb + 1 < nb) {
            int k0 = (kb + 1) << 5;
            cp_async16(&Xs[(buf^1)*128*GRS + lr*GRS + ls*4],
                       X + (size_t)(bm + lr) * K + k0 + ls*8);
            #pragma unroll
            for (int l = 0; l < 2; l++) {
                int idx = tid + l * 512;
                int r = idx >> 2;
                int s = idx & 3;
                cp_async16(&Ws[(buf^1)*256*GRS + r*GRS + s*4],
                           W + (size_t)(bn + r) * K + k0 + s*8);
            }
            cp_commit();
        }

        const uint32_t* xb = Xs + buf * 128 * GRS;
        const uint32_t* wb = Ws + buf * 256 * GRS;
        #pragma unroll
        for (int s = 0; s < 2; s++) {          // two k16 steps per BK=32
            const int so = s * 8;
            uint32_t afr[2][4];
            #pragma unroll
            for (int mt = 0; mt < 2; mt++) {
                int r0 = wm*32 + mt*16 + gid;
                afr[mt][0] = xb[r0*GRS + so + tg];
                afr[mt][1] = xb[(r0+8)*GRS + so + tg];
                afr[mt][2] = xb[r0*GRS + so + 4 + tg];
                afr[mt][3] = xb[(r0+8)*GRS + so + 4 + tg];
            }
            uint32_t bfr[8][2];
            #pragma unroll
            for (int nt = 0; nt < 8; nt++) {
                int nr = wn*64 + nt*8 + gid;
                bfr[nt][0] = wb[nr*GRS + so + tg];
                bfr[nt][1] = wb[nr*GRS + so + 4 + tg];
            }
            #pragma unroll
            for (int mt = 0; mt < 2; mt++)
                #pragma unroll
                for (int nt = 0; nt < 8; nt++)
                    mma_bf16(acc[mt][nt], afr[mt], bfr[nt]);
        }
        __syncthreads();
    }

    // epilogue
    #pragma unroll
    for (int mt = 0; mt < 2; mt++) {
        int m0 = bm + wm*32 + mt*16 + gid;
        int row0 = remap ? ((m0 & (Tq-1)) * Bq + (m0 >> 9)) : m0;
        int m1 = m0 + 8;
        int row1 = remap ? ((m1 & (Tq-1)) * Bq + (m1 >> 9)) : m1;
        #pragma unroll
        for (int nt = 0; nt < 8; nt++) {
            int c0 = bn + wn*64 + nt*8 + tg*2;
            float2 bv = *(const float2*)(bias + c0);
            float2 o0, o1;
            o0.x = acc[mt][nt][0] + bv.x; o0.y = acc[mt][nt][1] + bv.y;
            o1.x = acc[mt][nt][2] + bv.x; o1.y = acc[mt][nt][3] + bv.y;
            *(float2*)(Y + (size_t)row0 * Gq + c0) = o0;
            *(float2*)(Y + (size_t)row1 * Gq + c0) = o1;
        }
    }
}

// ============================================================
// Software grid barrier (all NBLK blocks resident by construction).
// ============================================================
__device__ __forceinline__ void gridbar(unsigned& myphase)
{
    __syncthreads();
    if (threadIdx.x == 0) {
        __threadfence();
        unsigned old = atomicAdd(&g_cnt, 1u);
        if (old == NBLK - 1) {
            g_cnt = 0;
            __threadfence();
            atomicAdd(&g_phase, 1u);
        } else {
            while (*(volatile unsigned*)&g_phase == myphase) { }
            __threadfence();
        }
    }
    __syncthreads();
    myphase++;
}

// ============================================================
// Persistent LSTM layer (best-measured config): 128 blocks x
// 256 threads, Whh slice in SMEM, FFMA2 GEMM, c in registers.
// ============================================================
__global__ void __launch_bounds__(256, 1)
lstm_layer(const float* __restrict__ xproj, const float* __restrict__ Whh,
           const float* __restrict__ bhh, float* __restrict__ hseq)
{
    extern __shared__ float smem[];
    float* Wsm = smem + WOFF;   // [32][WPAD]
    float* Hsm = smem + HOFF;   // [2][64][HPAD]
    float* Gsm = smem + GOFF;   // [64][36]
    float* Rsm = smem + HOFF;   // reduction scratch (unions with Hsm)

    const int tid = threadIdx.x;
    const int bid = blockIdx.x;
    const int j0  = bid * 8;

    unsigned myphase = *(volatile unsigned*)&g_phase;

    // ---- preload weight slice into smem: rows c=0..31 -> (gate=c>>3, jl=c&7)
    #pragma unroll
    for (int l = 0; l < 32; l++) {
        int idx = tid + l * 256;          // 0..8191 float4 slots
        int c  = idx >> 8;                // 256 float4 per row
        int kq = idx & 255;
        int grow = (c >> 3) * Hq + j0 + (c & 7);
        float4 v = *(const float4*)(Whh + (size_t)grow * Hq + kq * 4);
        *(float4*)(Wsm + c * WPAD + kq * 4) = v;
    }

    // GEMM coords
    const int ks  = tid >> 6;     // 0..3 k-split
    const int pos = tid & 63;
    const int bq  = pos >> 3;     // b = bq + 8i
    const int nq  = pos & 7;      // n = nq + 8j

    // update coords (2 items per thread)
    float creg[2] = {0.0f, 0.0f};
    float bh[2][4];
    #pragma unroll
    for (int q = 0; q < 2; q++) {
        int p = tid + q * 256;
        int jl = p & 7;
        #pragma unroll
        for (int g2 = 0; g2 < 4; g2++) bh[q][g2] = bhh[g2 * Hq + j0 + jl];
    }

    // zero h buffer 0
    {
        int idx = bid * 512 + tid;
        g_hbuf[0][idx] = 0.0f;
        g_hbuf[0][idx + 256] = 0.0f;
    }
    gridbar(myphase);

    for (int t = 0; t < Tq; t++) {
        const float* hprev = g_hbuf[t & 1];
        float* hnext = g_hbuf[(t + 1) & 1];

        // prefetch chunk 0 into buf 0
        #pragma unroll
        for (int l = 0; l < 8; l++) {
            int idx = tid + l * 256;      // 2048 float4
            int row = idx >> 5;
            int kq  = idx & 31;
            cp_async16(Hsm + row * HPAD + kq * 4,
                       hprev + (size_t)row * Hq + kq * 4);
        }
        cp_commit();

        // prefetch this step's xproj gate values (hidden behind GEMM)
        float xg[2][4];
        #pragma unroll
        for (int q = 0; q < 2; q++) {
            int p = tid + q * 256;
            int b = p >> 3, jl = p & 7;
            size_t xb = ((size_t)t * Bq + b) * Gq + j0 + jl;
            #pragma unroll
            for (int g2 = 0; g2 < 4; g2++) xg[q][g2] = xproj[xb + (size_t)g2 * Hq];
        }

        unsigned long long acc2[8][4] = {};
        for (int kc = 0; kc < 8; kc++) {
            const int buf = kc & 1;
            cp_wait0();
            __syncthreads();
            if (kc < 7) {
                float* hdst = Hsm + (buf ^ 1) * HBUF;
                #pragma unroll
                for (int l = 0; l < 8; l++) {
                    int idx = tid + l * 256;
                    int row = idx >> 5;
                    int kq  = idx & 31;
                    cp_async16(hdst + row * HPAD + kq * 4,
                               hprev + (size_t)row * Hq + (kc + 1) * 128 + kq * 4);
                }
                cp_commit();
            }

            const float* hb = Hsm + buf * HBUF + ks * 32;
            const float* wb = Wsm + kc * 128 + ks * 32;
            #pragma unroll
            for (int kk = 0; kk < 32; kk += 4) {
                ulonglong2 hq[8];
                #pragma unroll
                for (int i = 0; i < 8; i++)
                    hq[i] = *(const ulonglong2*)(hb + (bq + 8*i) * HPAD + kk);
                ulonglong2 wq[4];
                #pragma unroll
                for (int j = 0; j < 4; j++)
                    wq[j] = *(const ulonglong2*)(wb + (nq + 8*j) * WPAD + kk);
                #pragma unroll
                for (int i = 0; i < 8; i++)
                    #pragma unroll
                    for (int j = 0; j < 4; j++) {
                        acc2[i][j] = ffma2(hq[i].x, wq[j].x, acc2[i][j]);
                        acc2[i][j] = ffma2(hq[i].y, wq[j].y, acc2[i][j]);
                    }
            }
        }
        __syncthreads();   // all compute done; Hsm free for reduction

        // unpack even/odd-k partial sums
        float acc[8][4];
        #pragma unroll
        for (int i = 0; i < 8; i++)
            #pragma unroll
            for (int j = 0; j < 4; j++)
                acc[i][j] = u64lo(acc2[i][j]) + u64hi(acc2[i][j]);

        // k-split reduction through smem
        if (ks > 0) {
            float* rp = Rsm + ((ks - 1) * 64 + pos) * 36;
            #pragma unroll
            for (int i = 0; i < 8; i++)
                *(float4*)(rp + i * 4) = *(float4*)acc[i];
        }
        __syncthreads();
        if (ks == 0) {
            #pragma unroll
            for (int s = 0; s < 3; s++) {
                const float* rp = Rsm + (s * 64 + pos) * 36;
                #pragma unroll
                for (int i = 0; i < 8; i++) {
                    float4 v = *(const float4*)(rp + i * 4);
                    acc[i][0] += v.x; acc[i][1] += v.y;
                    acc[i][2] += v.z; acc[i][3] += v.w;
                }
            }
            #pragma unroll
            for (int i = 0; i < 8; i++) {
                int b = bq + 8*i;
                #pragma unroll
                for (int j = 0; j < 4; j++)
                    Gsm[b * 36 + nq + 8*j] = acc[i][j];
            }
        }
        __syncthreads();

        // pointwise LSTM update
        #pragma unroll
        for (int q = 0; q < 2; q++) {
            int p = tid + q * 256;
            int b = p >> 3, jl = p & 7;
            float gi = Gsm[b*36 +      jl] + xg[q][0] + bh[q][0];
            float gf = Gsm[b*36 +  8 + jl] + xg[q][1] + bh[q][1];
            float gg = Gsm[b*36 + 16 + jl] + xg[q][2] + bh[q][2];
            float go = Gsm[b*36 + 24 + jl] + xg[q][3] + bh[q][3];
            float ig = 1.0f / (1.0f + expf(-gi));
            float fg = 1.0f / (1.0f + expf(-gf));
            float gv = tanhf(gg);
            float og = 1.0f / (1.0f + expf(-go));
            float cn = fg * creg[q] + ig * gv;
            creg[q] = cn;
            float hn = og * tanhf(cn);
            hnext[(size_t)b * Hq + j0 + jl] = hn;
            hseq[((size_t)t * Bq + b) * Hq + j0 + jl] = hn;
        }
        gridbar(myphase);
    }
}

// ============================================================
// Emissions: e[(t*B+b), c] = h2_row . fc_w[c] + fc_b[c]; one warp/row.
// ============================================================
__global__ void emis_kernel(const float* __restrict__ h2, const float* __restrict__ fcw,
                            const float* __restrict__ fcb, float* __restrict__ e)
{
    int warp = (blockIdx.x * blockDim.x + threadIdx.x) >> 5;
    int lane = threadIdx.x & 31;
    if (warp >= MTOT) return;
    const float* hr = h2 + (size_t)warp * Hq;
    float acc[Cq];
    #pragma unroll
    for (int cc = 0; cc < Cq; cc++) acc[cc] = 0.0f;
    for (int k = lane; k < Hq; k += 32) {
        float hv = hr[k];
        #pragma unroll
        for (int cc = 0; cc < Cq; cc++)
            acc[cc] = fmaf(hv, fcw[cc*Hq + k], acc[cc]);
    }
    #pragma unroll
    for (int cc = 0; cc < Cq; cc++) {
        float v = acc[cc];
        #pragma unroll
        for (int off = 16; off; off >>= 1) v += __shfl_down_sync(0xffffffffu, v, off);
        if (lane == 0) e[(size_t)warp * Cq + cc] = v + fcb[cc];
    }
}

// ============================================================
// CRF NLL per batch element. One warp per b. emissions in (T,B,C).
// ============================================================
__global__ void crf_kernel(const float* __restrict__ e, const int* __restrict__ labels,
                           const float* __restrict__ startt, const float* __restrict__ endt,
                           const float* __restrict__ trans, float* __restrict__ llh)
{
    int b = blockIdx.x;
    int lane = threadIdx.x;
    const int* lb = labels + (size_t)b * Tq;

    // ---- path score ----
    float part = 0.0f;
    int cnt = 0;
    for (int t = 1 + lane; t < Tq; t += 32) {
        int tag  = lb[t];
        int tagp = lb[t-1];
        if (tag != -1)
            part += trans[tagp*Cq + tag] + e[((size_t)t*Bq + b)*Cq + tag];
    }
    for (int t = lane; t < Tq; t += 32) cnt += (lb[t] != -1);
    #pragma unroll
    for (int off = 16; off; off >>= 1) {
        part += __shfl_down_sync(0xffffffffu, part, off);
        cnt  += __shfl_down_sync(0xffffffffu, cnt, off);
    }
    float score = 0.0f;
    if (lane == 0) {
        int tag0 = lb[0];
        score = startt[tag0] + e[(size_t)b*Cq + tag0] + part;
        int last = cnt - 1;
        score += endt[lb[last]];
    }

    // ---- logZ (forward algorithm) ----
    __shared__ float alpha[Cq];
    float tcol[Cq];
    if (lane < Cq) {
        #pragma unroll
        for (int cc = 0; cc < Cq; cc++) tcol[cc] = trans[cc*Cq + lane];
        alpha[lane] = startt[lane] + e[(size_t)b*Cq + lane];
    }
    __syncwarp();
    for (int t = 1; t < Tq; t++) {
        bool m = (lb[t] != -1);
        float av[Cq];
        #pragma unroll
        for (int cc = 0; cc < Cq; cc++) av[cc] = alpha[cc];
        float nxt = 0.0f;
        if (lane < Cq) {
            float mx = -1e30f;
            #pragma unroll
            for (int cc = 0; cc < Cq; cc++) mx = fmaxf(mx, av[cc] + tcol[cc]);
            float s = 0.0f;
            #pragma unroll
            for (int cc = 0; cc < Cq; cc++) s += expf(av[cc] + tcol[cc] - mx);
            nxt = mx + logf(s) + e[((size_t)t*Bq + b)*Cq + lane];
        }
        __syncwarp();
        if (m && lane < Cq) alpha[lane] = nxt;
        __syncwarp();
    }
    float v = (lane < Cq) ? alpha[lane] + endt[lane] : -1e30f;
    float mx = v;
    #pragma unroll
    for (int off = 16; off; off >>= 1) mx = fmaxf(mx, __shfl_xor_sync(0xffffffffu, mx, off));
    float sv = (lane < Cq) ? expf(v - mx) : 0.0f;
    #pragma unroll
    for (int off = 16; off; off >>= 1) sv += __shfl_xor_sync(0xffffffffu, sv, off);
    if (lane == 0) llh[b] = score - (mx + logf(sv));
}

__global__ void finalize_kernel(const float* __restrict__ llh, float* __restrict__ out)
{
    __shared__ float s[64];
    int lane = threadIdx.x;
    s[lane] = llh[lane];
    __syncthreads();
    #pragma unroll
    for (int off = 32; off; off >>= 1) {
        if (lane < off) s[lane] += s[lane + off];
        __syncthreads();
    }
    if (lane == 0) out[0] = -s[0] / (float)Bq;
}

// ============================================================
extern "C" void kernel_launch(void* const* d_in, const int* in_sizes, int n_in,
                              void* d_out, int out_size)
{
    const float* x     = (const float*)d_in[0];
    const int*   labels= (const int*)  d_in[1];
    // d_in[2] = lengths (unused; reference derives mask from labels)
    const float* Wih0  = (const float*)d_in[3];
    const float* Whh0  = (const float*)d_in[4];
    const float* bih0  = (const float*)d_in[5];
    const float* bhh0  = (const float*)d_in[6];
    const float* Wih1  = (const float*)d_in[7];
    const float* Whh1  = (const float*)d_in[8];
    const float* bih1  = (const float*)d_in[9];
    const float* bhh1  = (const float*)d_in[10];
    const float* fcw   = (const float*)d_in[11];
    const float* fcb   = (const float*)d_in[12];
    const float* startt= (const float*)d_in[13];
    const float* endt  = (const float*)d_in[14];
    const float* trans = (const float*)d_in[15];

    float *xproj, *hseq1, *hseq2, *emis, *llh;
    __nv_bfloat16 *xb, *wb;
    cudaGetSymbolAddress((void**)&xproj, g_xproj);
    cudaGetSymbolAddress((void**)&hseq1, g_hseq1);
    cudaGetSymbolAddress((void**)&hseq2, g_hseq2);
    cudaGetSymbolAddress((void**)&xb,    g_xb);
    cudaGetSymbolAddress((void**)&wb,    g_wb);
    cudaGetSymbolAddress((void**)&emis,  g_emis);
    cudaGetSymbolAddress((void**)&llh,   g_llh);

    cudaFuncSetAttribute(lstm_layer, cudaFuncAttributeMaxDynamicSharedMemorySize, SMEM_BYTES);
    cudaFuncSetAttribute(sgemm_bf16, cudaFuncAttributeMaxDynamicSharedMemorySize, GEMM_SMEM_BYTES);

    dim3 gsX(Gq/256, MTOT/128);      // (16, 256)

    // ---- layer 1 ----
    cvt_bf16<<<(MTOT*Iq/4 + 255)/256, 256>>>(x, xb, MTOT*Iq/4);
    cvt_bf16<<<(Gq*Iq/4 + 255)/256, 256>>>(Wih0, wb, Gq*Iq/4);
    sgemm_bf16<<<gsX, 512, GEMM_SMEM_BYTES>>>(xb, wb, bih0, xproj, Iq, /*remap=*/1);
    lstm_layer<<<NBLK, 256, SMEM_BYTES>>>(xproj, Whh0, bhh0, hseq1);

    // ---- layer 2 ----
    cvt_bf16<<<(MTOT*Hq/4 + 255)/256, 256>>>(hseq1, xb, MTOT*Hq/4);
    cvt_bf16<<<(Gq*Hq/4 + 255)/256, 256>>>(Wih1, wb, Gq*Hq/4);
    sgemm_bf16<<<gsX, 512, GEMM_SMEM_BYTES>>>(xb, wb, bih1, xproj, Hq, /*remap=*/0);
    lstm_layer<<<NBLK, 256, SMEM_BYTES>>>(xproj, Whh1, bhh1, hseq2);

    // ---- emissions + CRF ----
    emis_kernel<<<(MTOT*32)/256, 256>>>(hseq2, fcw, fcb, emis);
    crf_kernel<<<Bq, 32>>>(emis, labels, startt, endt, trans, llh);
    finalize_kernel<<<1, 64>>>(llh, (float*)d_out);
}

// round 11
// speedup vs baseline: 3.3232x; 2.2626x over previous
#include <cuda_runtime.h>
#include <cuda_bf16.h>
#include <math.h>
#include <stdint.h>

// Problem constants
#define Bq 64
#define Tq 512
#define Iq 512
#define Hq 1024
#define Gq 4096      // 4*H
#define Cq 20
#define MTOT (Bq*Tq) // 32768
#define NBLK 128     // persistent blocks (<148 => all co-resident)

// sgemm_bf16 smem (uint32 words): Xs[2][128][20] + Ws[2][256][20]
#define GRS 20
#define GEMM_SMEM_WORDS (2*128*GRS + 2*256*GRS)
#define GEMM_SMEM_BYTES (GEMM_SMEM_WORDS * 4)    // 61440

// lstm_layer smem layout (uint32 words)
// Wsm: 32 rows x WSTR words (bf16 pairs; 1024 bf16 = 512 words + 4 pad)
// Hsm: 2 chunk buffers, each 64 rows x HCH words (256 bf16 = 128 words + 4 pad)
// Rsm: fp32 partials [2][64][36]
#define WSTR 516
#define HCH  132
#define HCHBUF (64*HCH)           // 8448 words
#define WOFF2 0
#define HOFF2 (32*WSTR)           // 16512
#define ROFF2 (HOFF2 + 2*HCHBUF)  // 33408
#define LSTM_SMEM_WORDS (ROFF2 + 2*64*36)
#define LSTM_SMEM_BYTES (LSTM_SMEM_WORDS * 4)    // 152064

// ---- scratch (static device allocations; no cudaMalloc allowed) ----
__device__ float g_xproj[(size_t)MTOT * Gq];   // 512 MB, reused by both layers
__device__ float g_hseq2[(size_t)MTOT * Hq];   // 134 MB (T,B,H) fp32 (layer-2 out)
__device__ __nv_bfloat16 g_xb[(size_t)MTOT * Hq];  // 64 MB bf16: layer-1 GEMM input, then layer-1 hseq out
__device__ __nv_bfloat16 g_wb[(size_t)Gq * Hq];    // 8 MB bf16 weights
__device__ __nv_bfloat16 g_hbufb[2][Bq * Hq];  // h ping-pong (bf16)
__device__ float g_emis[(size_t)MTOT * Cq];    // (T,B,C)
__device__ float g_llh[Bq];
__device__ unsigned g_cnt;
__device__ unsigned g_phase;

__device__ __forceinline__ void cp_async16(void* smem_dst, const void* gmem_src)
{
    uint32_t s = (uint32_t)__cvta_generic_to_shared(smem_dst);
    asm volatile("cp.async.cg.shared.global [%0], [%1], 16;\n" :: "r"(s), "l"(gmem_src));
}
__device__ __forceinline__ void cp_commit()
{
    asm volatile("cp.async.commit_group;\n");
}
__device__ __forceinline__ void cp_wait0()
{
    asm volatile("cp.async.wait_group 0;\n");
}

// bf16 MMA: D(16x8,f32) += A(16x16,row,bf16) * B(16x8,col,bf16)
__device__ __forceinline__ void mma_bf16(float* d, const uint32_t* a, const uint32_t* b)
{
    asm volatile(
        "mma.sync.aligned.m16n8k16.row.col.f32.bf16.bf16.f32 "
        "{%0,%1,%2,%3}, {%4,%5,%6,%7}, {%8,%9}, {%0,%1,%2,%3};"
        : "+f"(d[0]), "+f"(d[1]), "+f"(d[2]), "+f"(d[3])
        : "r"(a[0]), "r"(a[1]), "r"(a[2]), "r"(a[3]), "r"(b[0]), "r"(b[1]));
}

// ============================================================
// Elementwise fp32 -> bf16.
// ============================================================
__global__ void cvt_bf16(const float* __restrict__ src, __nv_bfloat16* __restrict__ dst,
                         int nquads)
{
    int i = blockIdx.x * blockDim.x + threadIdx.x;
    if (i >= nquads) return;
    float4 v = *(const float4*)(src + (size_t)i * 4);
    __nv_bfloat162 p0 = __floats2bfloat162_rn(v.x, v.y);
    __nv_bfloat162 p1 = __floats2bfloat162_rn(v.z, v.w);
    uint2 o;
    o.x = *(const uint32_t*)&p0;
    o.y = *(const uint32_t*)&p1;
    *(uint2*)(dst + (size_t)i * 4) = o;
}

// ============================================================
// bf16 tensor-core GEMM: Y = X(MxK)*W(NxK)^T + bias (fp32 out)
// Block tile 128m x 256n, BK=32, 512 threads, m16n8k16.
// If remap!=0, X row m = b*T+t and output row becomes t*B+b.
// ============================================================
__global__ void __launch_bounds__(512)
sgemm_bf16(const __nv_bfloat16* __restrict__ X, const __nv_bfloat16* __restrict__ W,
           const float* __restrict__ bias, float* __restrict__ Y,
           int K, int remap)
{
    extern __shared__ uint32_t gsm[];
    uint32_t* Xs = gsm;                 // [2][128][GRS]
    uint32_t* Ws = gsm + 2 * 128 * GRS; // [2][256][GRS]

    const int bn = blockIdx.x * 256;
    const int bm = blockIdx.y * 128;
    const int tid = threadIdx.x;
    const int warp = tid >> 5;
    const int lane = tid & 31;
    const int gid = lane >> 2;
    const int tg  = lane & 3;
    const int wm = warp >> 2;
    const int wn = warp & 3;

    const int lr = tid >> 2;
    const int ls = (tid & 3);

    float acc[2][8][4] = {};

    cp_async16(&Xs[0*128*GRS + lr*GRS + ls*4], X + (size_t)(bm + lr) * K + ls*8);
    #pragma unroll
    for (int l = 0; l < 2; l++) {
        int idx = tid + l * 512;
        int r = idx >> 2;
        int s = idx & 3;
        cp_async16(&Ws[0*256*GRS + r*GRS + s*4], W + (size_t)(bn + r) * K + s*8);
    }
    cp_commit();

    const int nb = K >> 5;
    for (int kb = 0; kb < nb; kb++) {
        const int buf = kb & 1;
        cp_wait0();
        __syncthreads();
        if (kb + 1 < nb) {
            int k0 = (kb + 1) << 5;
            cp_async16(&Xs[(buf^1)*128*GRS + lr*GRS + ls*4],
                       X + (size_t)(bm + lr) * K + k0 + ls*8);
            #pragma unroll
            for (int l = 0; l < 2; l++) {
                int idx = tid + l * 512;
                int r = idx >> 2;
                int s = idx & 3;
                cp_async16(&Ws[(buf^1)*256*GRS + r*GRS + s*4],
                           W + (size_t)(bn + r) * K + k0 + s*8);
            }
            cp_commit();
        }

        const uint32_t* xb = Xs + buf * 128 * GRS;
        const uint32_t* wb = Ws + buf * 256 * GRS;
        #pragma unroll
        for (int s = 0; s < 2; s++) {
            const int so = s * 8;
            uint32_t afr[2][4];
            #pragma unroll
            for (int mt = 0; mt < 2; mt++) {
                int r0 = wm*32 + mt*16 + gid;
                afr[mt][0] = xb[r0*GRS + so + tg];
                afr[mt][1] = xb[(r0+8)*GRS + so + tg];
                afr[mt][2] = xb[r0*GRS + so + 4 + tg];
                afr[mt][3] = xb[(r0+8)*GRS + so + 4 + tg];
            }
            uint32_t bfr[8][2];
            #pragma unroll
            for (int nt = 0; nt < 8; nt++) {
                int nr = wn*64 + nt*8 + gid;
                bfr[nt][0] = wb[nr*GRS + so + tg];
                bfr[nt][1] = wb[nr*GRS + so + 4 + tg];
            }
            #pragma unroll
            for (int mt = 0; mt < 2; mt++)
                #pragma unroll
                for (int nt = 0; nt < 8; nt++)
                    mma_bf16(acc[mt][nt], afr[mt], bfr[nt]);
        }
        __syncthreads();
    }

    #pragma unroll
    for (int mt = 0; mt < 2; mt++) {
        int m0 = bm + wm*32 + mt*16 + gid;
        int row0 = remap ? ((m0 & (Tq-1)) * Bq + (m0 >> 9)) : m0;
        int m1 = m0 + 8;
        int row1 = remap ? ((m1 & (Tq-1)) * Bq + (m1 >> 9)) : m1;
        #pragma unroll
        for (int nt = 0; nt < 8; nt++) {
            int c0 = bn + wn*64 + nt*8 + tg*2;
            float2 bv = *(const float2*)(bias + c0);
            float2 o0, o1;
            o0.x = acc[mt][nt][0] + bv.x; o0.y = acc[mt][nt][1] + bv.y;
            o1.x = acc[mt][nt][2] + bv.x; o1.y = acc[mt][nt][3] + bv.y;
            *(float2*)(Y + (size_t)row0 * Gq + c0) = o0;
            *(float2*)(Y + (size_t)row1 * Gq + c0) = o1;
        }
    }
}

// ============================================================
// Software grid barrier (all NBLK blocks resident by construction).
// ============================================================
__device__ __forceinline__ void gridbar(unsigned& myphase)
{
    __syncthreads();
    if (threadIdx.x == 0) {
        __threadfence();
        unsigned old = atomicAdd(&g_cnt, 1u);
        if (old == NBLK - 1) {
            g_cnt = 0;
            __threadfence();
            atomicAdd(&g_phase, 1u);
        } else {
            while (*(volatile unsigned*)&g_phase == myphase) { }
            __threadfence();
        }
    }
    __syncthreads();
    myphase++;
}

// ============================================================
// Persistent LSTM layer with bf16 tensor-core recurrent GEMM.
// 128 blocks x 256 threads (8 warps). Block owns 32 gate-cols
// (8 h-units x 4 gates). Whh slice bf16 in smem (66 KB) for all
// steps. h (bf16) streamed per step in 4 chunks of 256 k, double-
// buffered cp.async. Warp tile 32m x 16n, 2-way k-split; fp32
// partial reduction in smem. c fp32 in registers.
// hseq written as bf16 (hsb) and/or fp32 (hsf).
// ============================================================
__global__ void __launch_bounds__(256, 1)
lstm_layer(const float* __restrict__ xproj, const float* __restrict__ Whh,
           const float* __restrict__ bhh, float* __restrict__ hsf,
           __nv_bfloat16* __restrict__ hsb)
{
    extern __shared__ uint32_t sm2[];
    uint32_t* Wsm = sm2 + WOFF2;       // [32][WSTR] bf16-pair words
    uint32_t* Hsm = sm2 + HOFF2;       // [2][64][HCH]
    float*    Rsm = (float*)(sm2 + ROFF2);   // [2][64][36]

    const int tid = threadIdx.x;
    const int bid = blockIdx.x;
    const int j0  = bid * 8;

    unsigned myphase = *(volatile unsigned*)&g_phase;

    // ---- preload + convert weight slice to bf16 smem
    // rows c=0..31 -> global W row (gate=c>>3)*Hq + j0 + (c&7)
    #pragma unroll
    for (int l = 0; l < 32; l++) {
        int idx = tid + l * 256;          // 0..8191 float4 quads
        int c  = idx >> 8;                // 256 quads per row
        int kq = idx & 255;
        int grow = (c >> 3) * Hq + j0 + (c & 7);
        float4 v = *(const float4*)(Whh + (size_t)grow * Hq + kq * 4);
        __nv_bfloat162 p0 = __floats2bfloat162_rn(v.x, v.y);
        __nv_bfloat162 p1 = __floats2bfloat162_rn(v.z, v.w);
        Wsm[c * WSTR + kq * 2]     = *(const uint32_t*)&p0;
        Wsm[c * WSTR + kq * 2 + 1] = *(const uint32_t*)&p1;
    }

    // warp coords: ks = k-split half, wn2 = n-16 half, wm = m-32 half
    const int warp = tid >> 5;
    const int lane = tid & 31;
    const int gid = lane >> 2;
    const int tg  = lane & 3;
    const int ks  = warp & 1;
    const int wn2 = (warp >> 1) & 1;
    const int wm  = warp >> 2;

    // update coords (2 items per thread)
    float creg[2] = {0.0f, 0.0f};
    float bh[2][4];
    #pragma unroll
    for (int q = 0; q < 2; q++) {
        int p = tid + q * 256;
        int jl = p & 7;
        #pragma unroll
        for (int g2 = 0; g2 < 4; g2++) bh[q][g2] = bhh[g2 * Hq + j0 + jl];
    }

    // zero h buffer 0 (bf16): block's 512 bf16 = 256 words
    ((uint32_t*)g_hbufb[0])[bid * 256 + tid] = 0u;
    gridbar(myphase);

    for (int t = 0; t < Tq; t++) {
        const __nv_bfloat16* hprev = g_hbufb[t & 1];
        __nv_bfloat16* hnext = g_hbufb[(t + 1) & 1];

        // prefetch chunk 0 (64 rows x 256 bf16) into buf 0
        #pragma unroll
        for (int l = 0; l < 8; l++) {
            int idx = tid + l * 256;      // 0..2047
            int row = idx >> 5;
            int seg = idx & 31;
            cp_async16(Hsm + row * HCH + seg * 4,
                       hprev + (size_t)row * Hq + seg * 8);
        }
        cp_commit();

        // prefetch this step's xproj gate values (hidden behind GEMM)
        float xg[2][4];
        #pragma unroll
        for (int q = 0; q < 2; q++) {
            int p = tid + q * 256;
            int b = p >> 3, jl = p & 7;
            size_t xb = ((size_t)t * Bq + b) * Gq + j0 + jl;
            #pragma unroll
            for (int g2 = 0; g2 < 4; g2++) xg[q][g2] = xproj[xb + (size_t)g2 * Hq];
        }

        float acc[2][2][4] = {};
        for (int kc = 0; kc < 4; kc++) {
            const int buf = kc & 1;
            cp_wait0();
            __syncthreads();
            if (kc < 3) {
                uint32_t* hdst = Hsm + (buf ^ 1) * HCHBUF;
                #pragma unroll
                for (int l = 0; l < 8; l++) {
                    int idx = tid + l * 256;
                    int row = idx >> 5;
                    int seg = idx & 31;
                    cp_async16(hdst + row * HCH + seg * 4,
                               hprev + (size_t)row * Hq + (kc + 1) * 256 + seg * 8);
                }
                cp_commit();
            }

            const uint32_t* hb = Hsm + buf * HCHBUF;
            #pragma unroll
            for (int step = 0; step < 8; step++) {
                int kwc = ks * 64 + step * 8;          // word offset in chunk
                int kww = kc * 128 + kwc;              // word offset in full W row
                uint32_t afr[2][4];
                #pragma unroll
                for (int mt = 0; mt < 2; mt++) {
                    int r0 = wm * 32 + mt * 16 + gid;
                    afr[mt][0] = hb[r0 * HCH + kwc + tg];
                    afr[mt][1] = hb[(r0 + 8) * HCH + kwc + tg];
                    afr[mt][2] = hb[r0 * HCH + kwc + 4 + tg];
                    afr[mt][3] = hb[(r0 + 8) * HCH + kwc + 4 + tg];
                }
                uint32_t bfr[2][2];
                #pragma unroll
                for (int nt = 0; nt < 2; nt++) {
                    int nr = wn2 * 16 + nt * 8 + gid;
                    bfr[nt][0] = Wsm[nr * WSTR + kww + tg];
                    bfr[nt][1] = Wsm[nr * WSTR + kww + 4 + tg];
                }
                #pragma unroll
                for (int mt = 0; mt < 2; mt++)
                    #pragma unroll
                    for (int nt = 0; nt < 2; nt++)
                        mma_bf16(acc[mt][nt], afr[mt], bfr[nt]);
            }
        }

        // stash fp32 partials: Rsm[ks][row][col]
        #pragma unroll
        for (int mt = 0; mt < 2; mt++) {
            int r = wm * 32 + mt * 16 + gid;
            #pragma unroll
            for (int nt = 0; nt < 2; nt++) {
                int c = wn2 * 16 + nt * 8 + tg * 2;
                Rsm[ks * 2304 + r * 36 + c]           = acc[mt][nt][0];
                Rsm[ks * 2304 + r * 36 + c + 1]       = acc[mt][nt][1];
                Rsm[ks * 2304 + (r + 8) * 36 + c]     = acc[mt][nt][2];
                Rsm[ks * 2304 + (r + 8) * 36 + c + 1] = acc[mt][nt][3];
            }
        }
        __syncthreads();

        // pointwise LSTM update (2 items per thread)
        #pragma unroll
        for (int q = 0; q < 2; q++) {
            int p = tid + q * 256;
            int b = p >> 3, jl = p & 7;
            const float* r0p = Rsm + b * 36;
            const float* r1p = Rsm + 2304 + b * 36;
            float gi = r0p[jl]      + r1p[jl]      + xg[q][0] + bh[q][0];
            float gf = r0p[8 + jl]  + r1p[8 + jl]  + xg[q][1] + bh[q][1];
            float gg = r0p[16 + jl] + r1p[16 + jl] + xg[q][2] + bh[q][2];
            float go = r0p[24 + jl] + r1p[24 + jl] + xg[q][3] + bh[q][3];
            float ig = 1.0f / (1.0f + expf(-gi));
            float fg = 1.0f / (1.0f + expf(-gf));
            float gv = tanhf(gg);
            float og = 1.0f / (1.0f + expf(-go));
            float cn = fg * creg[q] + ig * gv;
            creg[q] = cn;
            float hn = og * tanhf(cn);
            hnext[(size_t)b * Hq + j0 + jl] = __float2bfloat16(hn);
            size_t so = ((size_t)t * Bq + b) * Hq + j0 + jl;
            if (hsf) hsf[so] = hn;
            if (hsb) hsb[so] = __float2bfloat16(hn);
        }
        gridbar(myphase);
    }
}

// ============================================================
// Emissions: e[(t*B+b), c] = h2_row . fc_w[c] + fc_b[c]; one warp/row.
// ============================================================
__global__ void emis_kernel(const float* __restrict__ h2, const float* __restrict__ fcw,
                            const float* __restrict__ fcb, float* __restrict__ e)
{
    int warp = (blockIdx.x * blockDim.x + threadIdx.x) >> 5;
    int lane = threadIdx.x & 31;
    if (warp >= MTOT) return;
    const float* hr = h2 + (size_t)warp * Hq;
    float acc[Cq];
    #pragma unroll
    for (int cc = 0; cc < Cq; cc++) acc[cc] = 0.0f;
    for (int k = lane; k < Hq; k += 32) {
        float hv = hr[k];
        #pragma unroll
        for (int cc = 0; cc < Cq; cc++)
            acc[cc] = fmaf(hv, fcw[cc*Hq + k], acc[cc]);
    }
    #pragma unroll
    for (int cc = 0; cc < Cq; cc++) {
        float v = acc[cc];
        #pragma unroll
        for (int off = 16; off; off >>= 1) v += __shfl_down_sync(0xffffffffu, v, off);
        if (lane == 0) e[(size_t)warp * Cq + cc] = v + fcb[cc];
    }
}

// ============================================================
// CRF NLL per batch element. One warp per b. emissions in (T,B,C).
// ============================================================
__global__ void crf_kernel(const float* __restrict__ e, const int* __restrict__ labels,
                           const float* __restrict__ startt, const float* __restrict__ endt,
                           const float* __restrict__ trans, float* __restrict__ llh)
{
    int b = blockIdx.x;
    int lane = threadIdx.x;
    const int* lb = labels + (size_t)b * Tq;

    // ---- path score ----
    float part = 0.0f;
    int cnt = 0;
    for (int t = 1 + lane; t < Tq; t += 32) {
        int tag  = lb[t];
        int tagp = lb[t-1];
        if (tag != -1)
            part += trans[tagp*Cq + tag] + e[((size_t)t*Bq + b)*Cq + tag];
    }
    for (int t = lane; t < Tq; t += 32) cnt += (lb[t] != -1);
    #pragma unroll
    for (int off = 16; off; off >>= 1) {
        part += __shfl_down_sync(0xffffffffu, part, off);
        cnt  += __shfl_down_sync(0xffffffffu, cnt, off);
    }
    float score = 0.0f;
    if (lane == 0) {
        int tag0 = lb[0];
        score = startt[tag0] + e[(size_t)b*Cq + tag0] + part;
        int last = cnt - 1;
        score += endt[lb[last]];
    }

    // ---- logZ (forward algorithm) ----
    __shared__ float alpha[Cq];
    float tcol[Cq];
    if (lane < Cq) {
        #pragma unroll
        for (int cc = 0; cc < Cq; cc++) tcol[cc] = trans[cc*Cq + lane];
        alpha[lane] = startt[lane] + e[(size_t)b*Cq + lane];
    }
    __syncwarp();
    for (int t = 1; t < Tq; t++) {
        bool m = (lb[t] != -1);
        float av[Cq];
        #pragma unroll
        for (int cc = 0; cc < Cq; cc++) av[cc] = alpha[cc];
        float nxt = 0.0f;
        if (lane < Cq) {
            float mx = -1e30f;
            #pragma unroll
            for (int cc = 0; cc < Cq; cc++) mx = fmaxf(mx, av[cc] + tcol[cc]);
            float s = 0.0f;
            #pragma unroll
            for (int cc = 0; cc < Cq; cc++) s += expf(av[cc] + tcol[cc] - mx);
            nxt = mx + logf(s) + e[((size_t)t*Bq + b)*Cq + lane];
        }
        __syncwarp();
        if (m && lane < Cq) alpha[lane] = nxt;
        __syncwarp();
    }
    float v = (lane < Cq) ? alpha[lane] + endt[lane] : -1e30f;
    float mx = v;
    #pragma unroll
    for (int off = 16; off; off >>= 1) mx = fmaxf(mx, __shfl_xor_sync(0xffffffffu, mx, off));
    float sv = (lane < Cq) ? expf(v - mx) : 0.0f;
    #pragma unroll
    for (int off = 16; off; off >>= 1) sv += __shfl_xor_sync(0xffffffffu, sv, off);
    if (lane == 0) llh[b] = score - (mx + logf(sv));
}

__global__ void finalize_kernel(const float* __restrict__ llh, float* __restrict__ out)
{
    __shared__ float s[64];
    int lane = threadIdx.x;
    s[lane] = llh[lane];
    __syncthreads();
    #pragma unroll
    for (int off = 32; off; off >>= 1) {
        if (lane < off) s[lane] += s[lane + off];
        __syncthreads();
    }
    if (lane == 0) out[0] = -s[0] / (float)Bq;
}

// ============================================================
extern "C" void kernel_launch(void* const* d_in, const int* in_sizes, int n_in,
                              void* d_out, int out_size)
{
    const float* x     = (const float*)d_in[0];
    const int*   labels= (const int*)  d_in[1];
    // d_in[2] = lengths (unused; reference derives mask from labels)
    const float* Wih0  = (const float*)d_in[3];
    const float* Whh0  = (const float*)d_in[4];
    const float* bih0  = (const float*)d_in[5];
    const float* bhh0  = (const float*)d_in[6];
    const float* Wih1  = (const float*)d_in[7];
    const float* Whh1  = (const float*)d_in[8];
    const float* bih1  = (const float*)d_in[9];
    const float* bhh1  = (const float*)d_in[10];
    const float* fcw   = (const float*)d_in[11];
    const float* fcb   = (const float*)d_in[12];
    const float* startt= (const float*)d_in[13];
    const float* endt  = (const float*)d_in[14];
    const float* trans = (const float*)d_in[15];

    float *xproj, *hseq2, *emis, *llh;
    __nv_bfloat16 *xb, *wb;
    cudaGetSymbolAddress((void**)&xproj, g_xproj);
    cudaGetSymbolAddress((void**)&hseq2, g_hseq2);
    cudaGetSymbolAddress((void**)&xb,    g_xb);
    cudaGetSymbolAddress((void**)&wb,    g_wb);
    cudaGetSymbolAddress((void**)&emis,  g_emis);
    cudaGetSymbolAddress((void**)&llh,   g_llh);

    cudaFuncSetAttribute(lstm_layer, cudaFuncAttributeMaxDynamicSharedMemorySize, LSTM_SMEM_BYTES);
    cudaFuncSetAttribute(sgemm_bf16, cudaFuncAttributeMaxDynamicSharedMemorySize, GEMM_SMEM_BYTES);

    dim3 gsX(Gq/256, MTOT/128);      // (16, 256)

    // ---- layer 1 ----
    cvt_bf16<<<(MTOT*Iq/4 + 255)/256, 256>>>(x, xb, MTOT*Iq/4);
    cvt_bf16<<<(Gq*Iq/4 + 255)/256, 256>>>(Wih0, wb, Gq*Iq/4);
    sgemm_bf16<<<gsX, 512, GEMM_SMEM_BYTES>>>(xb, wb, bih0, xproj, Iq, /*remap=*/1);
    // layer-1 hseq written directly as bf16 into xb (rows t*B+b) -> feeds layer-2 GEMM
    lstm_layer<<<NBLK, 256, LSTM_SMEM_BYTES>>>(xproj, Whh0, bhh0, (float*)nullptr, xb);

    // ---- layer 2 ----
    cvt_bf16<<<(Gq*Hq/4 + 255)/256, 256>>>(Wih1, wb, Gq*Hq/4);
    sgemm_bf16<<<gsX, 512, GEMM_SMEM_BYTES>>>(xb, wb, bih1, xproj, Hq, /*remap=*/0);
    lstm_layer<<<NBLK, 256, LSTM_SMEM_BYTES>>>(xproj, Whh1, bhh1, hseq2, (__nv_bfloat16*)nullptr);

    // ---- emissions + CRF ----
    emis_kernel<<<(MTOT*32)/256, 256>>>(hseq2, fcw, fcb, emis);
    crf_kernel<<<Bq, 32>>>(emis, labels, startt, endt, trans, llh);
    finalize_kernel<<<1, 64>>>(llh, (float*)d_out);
}

// round 12
// speedup vs baseline: 3.3725x; 1.0148x over previous
#include <cuda_runtime.h>
#include <cuda_bf16.h>
#include <math.h>
#include <stdint.h>

// Problem constants
#define Bq 64
#define Tq 512
#define Iq 512
#define Hq 1024
#define Gq 4096      // 4*H
#define Cq 20
#define MTOT (Bq*Tq) // 32768
#define NBLK 128     // persistent blocks (<148 => all co-resident)

// sgemm_bf16 smem (uint32 words): Xs[2][128][20] + Ws[2][128][20]
#define GRS 20
#define GEMM_SMEM_WORDS (2*128*GRS + 2*128*GRS)
#define GEMM_SMEM_BYTES (GEMM_SMEM_WORDS * 4)    // 40960

// lstm_layer smem layout (uint32 words)
// Wsm: 32 rows x WSTR words (1024 bf16 = 512 words + 4 pad)
// Hsm: 2 chunk buffers, each 64 rows x HCH words (512 bf16 = 256 words + 4 pad)
// Rsm: fp32 partials [2][64][36]
#define WSTR 516
#define HCH  260
#define HCHBUF (64*HCH)           // 16640 words
#define WOFF2 0
#define HOFF2 (32*WSTR)           // 16512
#define ROFF2 (HOFF2 + 2*HCHBUF)  // 49792
#define LSTM_SMEM_WORDS (ROFF2 + 2*64*36)
#define LSTM_SMEM_BYTES (LSTM_SMEM_WORDS * 4)    // 217600

// ---- scratch (static device allocations; no cudaMalloc allowed) ----
__device__ float g_xproj[(size_t)MTOT * Gq];   // 512 MB, reused by both layers
__device__ float g_hseq2[(size_t)MTOT * Hq];   // 134 MB (T,B,H) fp32 (layer-2 out)
__device__ __nv_bfloat16 g_xb[(size_t)MTOT * Hq];  // 64 MB bf16: layer-1 GEMM input, then layer-1 hseq out
__device__ __nv_bfloat16 g_wb[(size_t)Gq * Hq];    // 8 MB bf16 weights
__device__ __nv_bfloat16 g_hbufb[2][Bq * Hq];  // h ping-pong (bf16)
__device__ float g_emis[(size_t)MTOT * Cq];    // (T,B,C)
__device__ float g_llh[Bq];
__device__ unsigned g_cnt;
__device__ unsigned g_phase;

__device__ __forceinline__ void cp_async16(void* smem_dst, const void* gmem_src)
{
    uint32_t s = (uint32_t)__cvta_generic_to_shared(smem_dst);
    asm volatile("cp.async.cg.shared.global [%0], [%1], 16;\n" :: "r"(s), "l"(gmem_src));
}
__device__ __forceinline__ void cp_commit()
{
    asm volatile("cp.async.commit_group;\n");
}
__device__ __forceinline__ void cp_wait0()
{
    asm volatile("cp.async.wait_group 0;\n");
}

// bf16 MMA: D(16x8,f32) += A(16x16,row,bf16) * B(16x8,col,bf16)
__device__ __forceinline__ void mma_bf16(float* d, const uint32_t* a, const uint32_t* b)
{
    asm volatile(
        "mma.sync.aligned.m16n8k16.row.col.f32.bf16.bf16.f32 "
        "{%0,%1,%2,%3}, {%4,%5,%6,%7}, {%8,%9}, {%0,%1,%2,%3};"
        : "+f"(d[0]), "+f"(d[1]), "+f"(d[2]), "+f"(d[3])
        : "r"(a[0]), "r"(a[1]), "r"(a[2]), "r"(a[3]), "r"(b[0]), "r"(b[1]));
}

// ============================================================
// Elementwise fp32 -> bf16.
// ============================================================
__global__ void cvt_bf16(const float* __restrict__ src, __nv_bfloat16* __restrict__ dst,
                         int nquads)
{
    int i = blockIdx.x * blockDim.x + threadIdx.x;
    if (i >= nquads) return;
    float4 v = *(const float4*)(src + (size_t)i * 4);
    __nv_bfloat162 p0 = __floats2bfloat162_rn(v.x, v.y);
    __nv_bfloat162 p1 = __floats2bfloat162_rn(v.z, v.w);
    uint2 o;
    o.x = *(const uint32_t*)&p0;
    o.y = *(const uint32_t*)&p1;
    *(uint2*)(dst + (size_t)i * 4) = o;
}

// ============================================================
// bf16 tensor-core GEMM: Y = X(MxK)*W(NxK)^T + bias (fp32 out)
// Block tile 128m x 128n, BK=32, 256 threads (8 warps),
// warp tile 32m x 64n, m16n8k16. 2 CTAs/SM for latency overlap.
// If remap!=0, X row m = b*T+t and output row becomes t*B+b.
// ============================================================
__global__ void __launch_bounds__(256, 2)
sgemm_bf16(const __nv_bfloat16* __restrict__ X, const __nv_bfloat16* __restrict__ W,
           const float* __restrict__ bias, float* __restrict__ Y,
           int K, int remap)
{
    extern __shared__ uint32_t gsm[];
    uint32_t* Xs = gsm;                 // [2][128][GRS]
    uint32_t* Ws = gsm + 2 * 128 * GRS; // [2][128][GRS]

    const int bn = blockIdx.x * 128;
    const int bm = blockIdx.y * 128;
    const int tid = threadIdx.x;
    const int warp = tid >> 5;
    const int lane = tid & 31;
    const int gid = lane >> 2;
    const int tg  = lane & 3;
    const int wm = warp >> 1;        // 0..3 -> m0 = wm*32
    const int wn = warp & 1;         // 0..1 -> n0 = wn*64

    // tile-load coords: 2 cp.async per thread per operand
    const int lr0 = tid >> 1;            // 0..127 (two rows per thread pair)
    // each thread loads rows tid>>1 with seg = (tid&1)*2 + {0,1}
    float acc[2][8][4] = {};

    // prefetch tile 0
    #pragma unroll
    for (int l = 0; l < 2; l++) {
        int idx = tid + l * 256;          // 0..511 -> 128 rows x 4 segs
        int r = idx >> 2;
        int s = idx & 3;
        cp_async16(&Xs[0*128*GRS + r*GRS + s*4], X + (size_t)(bm + r) * K + s*8);
        cp_async16(&Ws[0*128*GRS + r*GRS + s*4], W + (size_t)(bn + r) * K + s*8);
    }
    cp_commit();
    (void)lr0;

    const int nb = K >> 5;
    for (int kb = 0; kb < nb; kb++) {
        const int buf = kb & 1;
        cp_wait0();
        __syncthreads();
        if (kb + 1 < nb) {
            int k0 = (kb + 1) << 5;
            #pragma unroll
            for (int l = 0; l < 2; l++) {
                int idx = tid + l * 256;
                int r = idx >> 2;
                int s = idx & 3;
                cp_async16(&Xs[(buf^1)*128*GRS + r*GRS + s*4],
                           X + (size_t)(bm + r) * K + k0 + s*8);
                cp_async16(&Ws[(buf^1)*128*GRS + r*GRS + s*4],
                           W + (size_t)(bn + r) * K + k0 + s*8);
            }
            cp_commit();
        }

        const uint32_t* xb = Xs + buf * 128 * GRS;
        const uint32_t* wb = Ws + buf * 128 * GRS;
        #pragma unroll
        for (int s = 0; s < 2; s++) {
            const int so = s * 8;
            uint32_t afr[2][4];
            #pragma unroll
            for (int mt = 0; mt < 2; mt++) {
                int r0 = wm*32 + mt*16 + gid;
                afr[mt][0] = xb[r0*GRS + so + tg];
                afr[mt][1] = xb[(r0+8)*GRS + so + tg];
                afr[mt][2] = xb[r0*GRS + so + 4 + tg];
                afr[mt][3] = xb[(r0+8)*GRS + so + 4 + tg];
            }
            uint32_t bfr[8][2];
            #pragma unroll
            for (int nt = 0; nt < 8; nt++) {
                int nr = wn*64 + nt*8 + gid;
                bfr[nt][0] = wb[nr*GRS + so + tg];
                bfr[nt][1] = wb[nr*GRS + so + 4 + tg];
            }
            #pragma unroll
            for (int mt = 0; mt < 2; mt++)
                #pragma unroll
                for (int nt = 0; nt < 8; nt++)
                    mma_bf16(acc[mt][nt], afr[mt], bfr[nt]);
        }
        __syncthreads();
    }

    #pragma unroll
    for (int mt = 0; mt < 2; mt++) {
        int m0 = bm + wm*32 + mt*16 + gid;
        int row0 = remap ? ((m0 & (Tq-1)) * Bq + (m0 >> 9)) : m0;
        int m1 = m0 + 8;
        int row1 = remap ? ((m1 & (Tq-1)) * Bq + (m1 >> 9)) : m1;
        #pragma unroll
        for (int nt = 0; nt < 8; nt++) {
            int c0 = bn + wn*64 + nt*8 + tg*2;
            float2 bv = *(const float2*)(bias + c0);
            float2 o0, o1;
            o0.x = acc[mt][nt][0] + bv.x; o0.y = acc[mt][nt][1] + bv.y;
            o1.x = acc[mt][nt][2] + bv.x; o1.y = acc[mt][nt][3] + bv.y;
            *(float2*)(Y + (size_t)row0 * Gq + c0) = o0;
            *(float2*)(Y + (size_t)row1 * Gq + c0) = o1;
        }
    }
}

// ============================================================
// Software grid barrier (all NBLK blocks resident by construction).
// ============================================================
__device__ __forceinline__ void gridbar(unsigned& myphase)
{
    __syncthreads();
    if (threadIdx.x == 0) {
        __threadfence();
        unsigned old = atomicAdd(&g_cnt, 1u);
        if (old == NBLK - 1) {
            g_cnt = 0;
            __threadfence();
            atomicAdd(&g_phase, 1u);
        } else {
            while (*(volatile unsigned*)&g_phase == myphase) { }
            __threadfence();
        }
    }
    __syncthreads();
    myphase++;
}

// ============================================================
// Persistent LSTM layer with bf16 tensor-core recurrent GEMM.
// 128 blocks x 256 threads (8 warps). Block owns 32 gate-cols.
// Whh slice bf16 in smem for all steps. h (bf16) streamed per
// step in 2 chunks of 512 k, double-buffered cp.async. Warp tile
// 32m x 16n, 2-way k-split; fp32 partial reduce in smem.
// c fp32 in registers. hseq written bf16 (hsb) and/or fp32 (hsf).
// ============================================================
__global__ void __launch_bounds__(256, 1)
lstm_layer(const float* __restrict__ xproj, const float* __restrict__ Whh,
           const float* __restrict__ bhh, float* __restrict__ hsf,
           __nv_bfloat16* __restrict__ hsb)
{
    extern __shared__ uint32_t sm2[];
    uint32_t* Wsm = sm2 + WOFF2;       // [32][WSTR]
    uint32_t* Hsm = sm2 + HOFF2;       // [2][64][HCH]
    float*    Rsm = (float*)(sm2 + ROFF2);   // [2][64][36]

    const int tid = threadIdx.x;
    const int bid = blockIdx.x;
    const int j0  = bid * 8;

    unsigned myphase = *(volatile unsigned*)&g_phase;

    // ---- preload + convert weight slice to bf16 smem
    #pragma unroll
    for (int l = 0; l < 32; l++) {
        int idx = tid + l * 256;          // 0..8191 float4 quads
        int c  = idx >> 8;
        int kq = idx & 255;
        int grow = (c >> 3) * Hq + j0 + (c & 7);
        float4 v = *(const float4*)(Whh + (size_t)grow * Hq + kq * 4);
        __nv_bfloat162 p0 = __floats2bfloat162_rn(v.x, v.y);
        __nv_bfloat162 p1 = __floats2bfloat162_rn(v.z, v.w);
        Wsm[c * WSTR + kq * 2]     = *(const uint32_t*)&p0;
        Wsm[c * WSTR + kq * 2 + 1] = *(const uint32_t*)&p1;
    }

    const int warp = tid >> 5;
    const int lane = tid & 31;
    const int gid = lane >> 2;
    const int tg  = lane & 3;
    const int ks  = warp & 1;          // k-split half
    const int wn2 = (warp >> 1) & 1;   // n-16 half
    const int wm  = warp >> 2;         // m-32 half

    float creg[2] = {0.0f, 0.0f};
    float bh[2][4];
    #pragma unroll
    for (int q = 0; q < 2; q++) {
        int p = tid + q * 256;
        int jl = p & 7;
        #pragma unroll
        for (int g2 = 0; g2 < 4; g2++) bh[q][g2] = bhh[g2 * Hq + j0 + jl];
    }

    ((uint32_t*)g_hbufb[0])[bid * 256 + tid] = 0u;
    gridbar(myphase);

    for (int t = 0; t < Tq; t++) {
        const __nv_bfloat16* hprev = g_hbufb[t & 1];
        __nv_bfloat16* hnext = g_hbufb[(t + 1) & 1];

        // prefetch chunk 0 (64 rows x 512 bf16 = 4096 cp16) into buf 0
        #pragma unroll
        for (int l = 0; l < 16; l++) {
            int idx = tid + l * 256;      // 0..4095
            int row = idx >> 6;
            int seg = idx & 63;
            cp_async16(Hsm + row * HCH + seg * 4,
                       hprev + (size_t)row * Hq + seg * 8);
        }
        cp_commit();

        // prefetch this step's xproj gate values (hidden behind GEMM)
        float xg[2][4];
        #pragma unroll
        for (int q = 0; q < 2; q++) {
            int p = tid + q * 256;
            int b = p >> 3, jl = p & 7;
            size_t xb = ((size_t)t * Bq + b) * Gq + j0 + jl;
            #pragma unroll
            for (int g2 = 0; g2 < 4; g2++) xg[q][g2] = xproj[xb + (size_t)g2 * Hq];
        }

        float acc[2][2][4] = {};
        for (int kc = 0; kc < 2; kc++) {
            const int buf = kc & 1;
            cp_wait0();
            __syncthreads();
            if (kc == 0) {
                uint32_t* hdst = Hsm + HCHBUF;
                #pragma unroll
                for (int l = 0; l < 16; l++) {
                    int idx = tid + l * 256;
                    int row = idx >> 6;
                    int seg = idx & 63;
                    cp_async16(hdst + row * HCH + seg * 4,
                               hprev + (size_t)row * Hq + 512 + seg * 8);
                }
                cp_commit();
            }

            const uint32_t* hb = Hsm + buf * HCHBUF;
            #pragma unroll
            for (int step = 0; step < 16; step++) {
                int kwc = ks * 128 + step * 8;          // word offset in chunk (256 words)
                int kww = kc * 256 + kwc;               // word offset in full W row
                uint32_t afr[2][4];
                #pragma unroll
                for (int mt = 0; mt < 2; mt++) {
                    int r0 = wm * 32 + mt * 16 + gid;
                    afr[mt][0] = hb[r0 * HCH + kwc + tg];
                    afr[mt][1] = hb[(r0 + 8) * HCH + kwc + tg];
                    afr[mt][2] = hb[r0 * HCH + kwc + 4 + tg];
                    afr[mt][3] = hb[(r0 + 8) * HCH + kwc + 4 + tg];
                }
                uint32_t bfr[2][2];
                #pragma unroll
                for (int nt = 0; nt < 2; nt++) {
                    int nr = wn2 * 16 + nt * 8 + gid;
                    bfr[nt][0] = Wsm[nr * WSTR + kww + tg];
                    bfr[nt][1] = Wsm[nr * WSTR + kww + 4 + tg];
                }
                #pragma unroll
                for (int mt = 0; mt < 2; mt++)
                    #pragma unroll
                    for (int nt = 0; nt < 2; nt++)
                        mma_bf16(acc[mt][nt], afr[mt], bfr[nt]);
            }
        }

        // stash fp32 partials: Rsm[ks][row][col]
        #pragma unroll
        for (int mt = 0; mt < 2; mt++) {
            int r = wm * 32 + mt * 16 + gid;
            #pragma unroll
            for (int nt = 0; nt < 2; nt++) {
                int c = wn2 * 16 + nt * 8 + tg * 2;
                Rsm[ks * 2304 + r * 36 + c]           = acc[mt][nt][0];
                Rsm[ks * 2304 + r * 36 + c + 1]       = acc[mt][nt][1];
                Rsm[ks * 2304 + (r + 8) * 36 + c]     = acc[mt][nt][2];
                Rsm[ks * 2304 + (r + 8) * 36 + c + 1] = acc[mt][nt][3];
            }
        }
        __syncthreads();

        // pointwise LSTM update (2 items per thread)
        #pragma unroll
        for (int q = 0; q < 2; q++) {
            int p = tid + q * 256;
            int b = p >> 3, jl = p & 7;
            const float* r0p = Rsm + b * 36;
            const float* r1p = Rsm + 2304 + b * 36;
            float gi = r0p[jl]      + r1p[jl]      + xg[q][0] + bh[q][0];
            float gf = r0p[8 + jl]  + r1p[8 + jl]  + xg[q][1] + bh[q][1];
            float gg = r0p[16 + jl] + r1p[16 + jl] + xg[q][2] + bh[q][2];
            float go = r0p[24 + jl] + r1p[24 + jl] + xg[q][3] + bh[q][3];
            float ig = 1.0f / (1.0f + expf(-gi));
            float fg = 1.0f / (1.0f + expf(-gf));
            float gv = tanhf(gg);
            float og = 1.0f / (1.0f + expf(-go));
            float cn = fg * creg[q] + ig * gv;
            creg[q] = cn;
            float hn = og * tanhf(cn);
            hnext[(size_t)b * Hq + j0 + jl] = __float2bfloat16(hn);
            size_t so = ((size_t)t * Bq + b) * Hq + j0 + jl;
            if (hsf) hsf[so] = hn;
            if (hsb) hsb[so] = __float2bfloat16(hn);
        }
        gridbar(myphase);
    }
}

// ============================================================
// Emissions: e[(t*B+b), c] = h2_row . fc_w[c] + fc_b[c]; one warp/row.
// ============================================================
__global__ void emis_kernel(const float* __restrict__ h2, const float* __restrict__ fcw,
                            const float* __restrict__ fcb, float* __restrict__ e)
{
    int warp = (blockIdx.x * blockDim.x + threadIdx.x) >> 5;
    int lane = threadIdx.x & 31;
    if (warp >= MTOT) return;
    const float* hr = h2 + (size_t)warp * Hq;
    float acc[Cq];
    #pragma unroll
    for (int cc = 0; cc < Cq; cc++) acc[cc] = 0.0f;
    for (int k = lane; k < Hq; k += 32) {
        float hv = hr[k];
        #pragma unroll
        for (int cc = 0; cc < Cq; cc++)
            acc[cc] = fmaf(hv, fcw[cc*Hq + k], acc[cc]);
    }
    #pragma unroll
    for (int cc = 0; cc < Cq; cc++) {
        float v = acc[cc];
        #pragma unroll
        for (int off = 16; off; off >>= 1) v += __shfl_down_sync(0xffffffffu, v, off);
        if (lane == 0) e[(size_t)warp * Cq + cc] = v + fcb[cc];
    }
}

// ============================================================
// CRF NLL per batch element. One warp per b. emissions in (T,B,C).
// ============================================================
__global__ void crf_kernel(const float* __restrict__ e, const int* __restrict__ labels,
                           const float* __restrict__ startt, const float* __restrict__ endt,
                           const float* __restrict__ trans, float* __restrict__ llh)
{
    int b = blockIdx.x;
    int lane = threadIdx.x;
    const int* lb = labels + (size_t)b * Tq;

    // ---- path score ----
    float part = 0.0f;
    int cnt = 0;
    for (int t = 1 + lane; t < Tq; t += 32) {
        int tag  = lb[t];
        int tagp = lb[t-1];
        if (tag != -1)
            part += trans[tagp*Cq + tag] + e[((size_t)t*Bq + b)*Cq + tag];
    }
    for (int t = lane; t < Tq; t += 32) cnt += (lb[t] != -1);
    #pragma unroll
    for (int off = 16; off; off >>= 1) {
        part += __shfl_down_sync(0xffffffffu, part, off);
        cnt  += __shfl_down_sync(0xffffffffu, cnt, off);
    }
    float score = 0.0f;
    if (lane == 0) {
        int tag0 = lb[0];
        score = startt[tag0] + e[(size_t)b*Cq + tag0] + part;
        int last = cnt - 1;
        score += endt[lb[last]];
    }

    // ---- logZ (forward algorithm) ----
    __shared__ float alpha[Cq];
    float tcol[Cq];
    if (lane < Cq) {
        #pragma unroll
        for (int cc = 0; cc < Cq; cc++) tcol[cc] = trans[cc*Cq + lane];
        alpha[lane] = startt[lane] + e[(size_t)b*Cq + lane];
    }
    __syncwarp();
    for (int t = 1; t < Tq; t++) {
        bool m = (lb[t] != -1);
        float av[Cq];
        #pragma unroll
        for (int cc = 0; cc < Cq; cc++) av[cc] = alpha[cc];
        float nxt = 0.0f;
        if (lane < Cq) {
            float mx = -1e30f;
            #pragma unroll
            for (int cc = 0; cc < Cq; cc++) mx = fmaxf(mx, av[cc] + tcol[cc]);
            float s = 0.0f;
            #pragma unroll
            for (int cc = 0; cc < Cq; cc++) s += expf(av[cc] + tcol[cc] - mx);
            nxt = mx + logf(s) + e[((size_t)t*Bq + b)*Cq + lane];
        }
        __syncwarp();
        if (m && lane < Cq) alpha[lane] = nxt;
        __syncwarp();
    }
    float v = (lane < Cq) ? alpha[lane] + endt[lane] : -1e30f;
    float mx = v;
    #pragma unroll
    for (int off = 16; off; off >>= 1) mx = fmaxf(mx, __shfl_xor_sync(0xffffffffu, mx, off));
    float sv = (lane < Cq) ? expf(v - mx) : 0.0f;
    #pragma unroll
    for (int off = 16; off; off >>= 1) sv += __shfl_xor_sync(0xffffffffu, sv, off);
    if (lane == 0) llh[b] = score - (mx + logf(sv));
}

__global__ void finalize_kernel(const float* __restrict__ llh, float* __restrict__ out)
{
    __shared__ float s[64];
    int lane = threadIdx.x;
    s[lane] = llh[lane];
    __syncthreads();
    #pragma unroll
    for (int off = 32; off; off >>= 1) {
        if (lane < off) s[lane] += s[lane + off];
        __syncthreads();
    }
    if (lane == 0) out[0] = -s[0] / (float)Bq;
}

// ============================================================
extern "C" void kernel_launch(void* const* d_in, const int* in_sizes, int n_in,
                              void* d_out, int out_size)
{
    const float* x     = (const float*)d_in[0];
    const int*   labels= (const int*)  d_in[1];
    // d_in[2] = lengths (unused; reference derives mask from labels)
    const float* Wih0  = (const float*)d_in[3];
    const float* Whh0  = (const float*)d_in[4];
    const float* bih0  = (const float*)d_in[5];
    const float* bhh0  = (const float*)d_in[6];
    const float* Wih1  = (const float*)d_in[7];
    const float* Whh1  = (const float*)d_in[8];
    const float* bih1  = (const float*)d_in[9];
    const float* bhh1  = (const float*)d_in[10];
    const float* fcw   = (const float*)d_in[11];
    const float* fcb   = (const float*)d_in[12];
    const float* startt= (const float*)d_in[13];
    const float* endt  = (const float*)d_in[14];
    const float* trans = (const float*)d_in[15];

    float *xproj, *hseq2, *emis, *llh;
    __nv_bfloat16 *xb, *wb;
    cudaGetSymbolAddress((void**)&xproj, g_xproj);
    cudaGetSymbolAddress((void**)&hseq2, g_hseq2);
    cudaGetSymbolAddress((void**)&xb,    g_xb);
    cudaGetSymbolAddress((void**)&wb,    g_wb);
    cudaGetSymbolAddress((void**)&emis,  g_emis);
    cudaGetSymbolAddress((void**)&llh,   g_llh);

    cudaFuncSetAttribute(lstm_layer, cudaFuncAttributeMaxDynamicSharedMemorySize, LSTM_SMEM_BYTES);
    cudaFuncSetAttribute(sgemm_bf16, cudaFuncAttributeMaxDynamicSharedMemorySize, GEMM_SMEM_BYTES);

    dim3 gsX(Gq/128, MTOT/128);      // (32, 256)

    // ---- layer 1 ----
    cvt_bf16<<<(MTOT*Iq/4 + 255)/256, 256>>>(x, xb, MTOT*Iq/4);
    cvt_bf16<<<(Gq*Iq/4 + 255)/256, 256>>>(Wih0, wb, Gq*Iq/4);
    sgemm_bf16<<<gsX, 256, GEMM_SMEM_BYTES>>>(xb, wb, bih0, xproj, Iq, /*remap=*/1);
    // layer-1 hseq written directly as bf16 into xb (rows t*B+b) -> feeds layer-2 GEMM
    lstm_layer<<<NBLK, 256, LSTM_SMEM_BYTES>>>(xproj, Whh0, bhh0, (float*)nullptr, xb);

    // ---- layer 2 ----
    cvt_bf16<<<(Gq*Hq/4 + 255)/256, 256>>>(Wih1, wb, Gq*Hq/4);
    sgemm_bf16<<<gsX, 256, GEMM_SMEM_BYTES>>>(xb, wb, bih1, xproj, Hq, /*remap=*/0);
    lstm_layer<<<NBLK, 256, LSTM_SMEM_BYTES>>>(xproj, Whh1, bhh1, hseq2, (__nv_bfloat16*)nullptr);

    // ---- emissions + CRF ----
    emis_kernel<<<(MTOT*32)/256, 256>>>(hseq2, fcw, fcb, emis);
    crf_kernel<<<Bq, 32>>>(emis, labels, startt, endt, trans, llh);
    finalize_kernel<<<1, 64>>>(llh, (float*)d_out);
}

// round 13
// speedup vs baseline: 3.4977x; 1.0371x over previous
#include <cuda_runtime.h>
#include <cuda_bf16.h>
#include <math.h>
#include <stdint.h>

// Problem constants
#define Bq 64
#define Tq 512
#define Iq 512
#define Hq 1024
#define Gq 4096      // 4*H
#define Cq 20
#define MTOT (Bq*Tq) // 32768
#define NBLK 128     // persistent blocks (<148 => all co-resident)

// sgemm_bf16 smem (uint32 words): 3-stage Xs[3][128][20] + Ws[3][128][20]
#define GRS 20
#define GEMM_SMEM_WORDS (3*128*GRS + 3*128*GRS)
#define GEMM_SMEM_BYTES (GEMM_SMEM_WORDS * 4)    // 61440

// lstm_layer smem layout (uint32 words)
#define WSTR 516
#define HCH  260
#define HCHBUF (64*HCH)           // 16640 words
#define WOFF2 0
#define HOFF2 (32*WSTR)           // 16512
#define ROFF2 (HOFF2 + 2*HCHBUF)  // 49792
#define LSTM_SMEM_WORDS (ROFF2 + 2*64*36)
#define LSTM_SMEM_BYTES (LSTM_SMEM_WORDS * 4)    // 217600

// ---- scratch (static device allocations; no cudaMalloc allowed) ----
__device__ float g_xproj[(size_t)MTOT * Gq];   // 512 MB, reused by both layers
__device__ float g_hseq2[(size_t)MTOT * Hq];   // 134 MB (T,B,H) fp32 (layer-2 out)
__device__ __nv_bfloat16 g_xb[(size_t)MTOT * Hq];  // 64 MB bf16
__device__ __nv_bfloat16 g_wb[(size_t)Gq * Hq];    // 8 MB bf16 weights
__device__ __nv_bfloat16 g_hbufb[2][Bq * Hq];  // h ping-pong (bf16)
__device__ float g_emis[(size_t)MTOT * Cq];    // (T,B,C)
__device__ float g_llh[Bq];
__device__ unsigned g_flags[NBLK * 32];        // distributed barrier flags (128B apart)

__device__ __forceinline__ void cp_async16(void* smem_dst, const void* gmem_src)
{
    uint32_t s = (uint32_t)__cvta_generic_to_shared(smem_dst);
    asm volatile("cp.async.cg.shared.global [%0], [%1], 16;\n" :: "r"(s), "l"(gmem_src));
}
__device__ __forceinline__ void cp_commit()
{
    asm volatile("cp.async.commit_group;\n");
}
__device__ __forceinline__ void cp_wait0()
{
    asm volatile("cp.async.wait_group 0;\n");
}
__device__ __forceinline__ void cp_wait1()
{
    asm volatile("cp.async.wait_group 1;\n");
}

// bf16 MMA: D(16x8,f32) += A(16x16,row,bf16) * B(16x8,col,bf16)
__device__ __forceinline__ void mma_bf16(float* d, const uint32_t* a, const uint32_t* b)
{
    asm volatile(
        "mma.sync.aligned.m16n8k16.row.col.f32.bf16.bf16.f32 "
        "{%0,%1,%2,%3}, {%4,%5,%6,%7}, {%8,%9}, {%0,%1,%2,%3};"
        : "+f"(d[0]), "+f"(d[1]), "+f"(d[2]), "+f"(d[3])
        : "r"(a[0]), "r"(a[1]), "r"(a[2]), "r"(a[3]), "r"(b[0]), "r"(b[1]));
}

// ============================================================
// Elementwise fp32 -> bf16.
// ============================================================
__global__ void cvt_bf16(const float* __restrict__ src, __nv_bfloat16* __restrict__ dst,
                         int nquads)
{
    int i = blockIdx.x * blockDim.x + threadIdx.x;
    if (i >= nquads) return;
    float4 v = *(const float4*)(src + (size_t)i * 4);
    __nv_bfloat162 p0 = __floats2bfloat162_rn(v.x, v.y);
    __nv_bfloat162 p1 = __floats2bfloat162_rn(v.z, v.w);
    uint2 o;
    o.x = *(const uint32_t*)&p0;
    o.y = *(const uint32_t*)&p1;
    *(uint2*)(dst + (size_t)i * 4) = o;
}

// ============================================================
// bf16 tensor-core GEMM: Y = X(MxK)*W(NxK)^T + bias (fp32 out)
// Block tile 128m x 128n, BK=32, 256 threads (8 warps),
// warp tile 32m x 64n, m16n8k16. 3-stage cp.async pipeline
// (wait_group 1), 2 CTAs/SM.
// If remap!=0, X row m = b*T+t and output row becomes t*B+b.
// ============================================================
__global__ void __launch_bounds__(256, 2)
sgemm_bf16(const __nv_bfloat16* __restrict__ X, const __nv_bfloat16* __restrict__ W,
           const float* __restrict__ bias, float* __restrict__ Y,
           int K, int remap)
{
    extern __shared__ uint32_t gsm[];
    uint32_t* Xs = gsm;                 // [3][128][GRS]
    uint32_t* Ws = gsm + 3 * 128 * GRS; // [3][128][GRS]

    const int bn = blockIdx.x * 128;
    const int bm = blockIdx.y * 128;
    const int tid = threadIdx.x;
    const int warp = tid >> 5;
    const int lane = tid & 31;
    const int gid = lane >> 2;
    const int tg  = lane & 3;
    const int wm = warp >> 1;        // 0..3 -> m0 = wm*32
    const int wn = warp & 1;         // 0..1 -> n0 = wn*64

    float acc[2][8][4] = {};
    const int nb = K >> 5;

    // prefetch tiles 0 and 1 (separate commit groups)
    #pragma unroll
    for (int p = 0; p < 2; p++) {
        if (p < nb) {
            int k0 = p << 5;
            #pragma unroll
            for (int l = 0; l < 2; l++) {
                int idx = tid + l * 256;
                int r = idx >> 2;
                int s = idx & 3;
                cp_async16(&Xs[p*128*GRS + r*GRS + s*4], X + (size_t)(bm + r) * K + k0 + s*8);
                cp_async16(&Ws[p*128*GRS + r*GRS + s*4], W + (size_t)(bn + r) * K + k0 + s*8);
            }
            cp_commit();
        }
    }

    for (int kb = 0; kb < nb; kb++) {
        const int buf = kb % 3;
        cp_wait1();              // tile kb complete (kb+1 may be in flight)
        __syncthreads();         // also guards reuse of buffer (kb+2)%3
        if (kb + 2 < nb) {
            int k0 = (kb + 2) << 5;
            int pb = (kb + 2) % 3;
            #pragma unroll
            for (int l = 0; l < 2; l++) {
                int idx = tid + l * 256;
                int r = idx >> 2;
                int s = idx & 3;
                cp_async16(&Xs[pb*128*GRS + r*GRS + s*4],
                           X + (size_t)(bm + r) * K + k0 + s*8);
                cp_async16(&Ws[pb*128*GRS + r*GRS + s*4],
                           W + (size_t)(bn + r) * K + k0 + s*8);
            }
            cp_commit();
        }

        const uint32_t* xb = Xs + buf * 128 * GRS;
        const uint32_t* wb = Ws + buf * 128 * GRS;
        #pragma unroll
        for (int s = 0; s < 2; s++) {
            const int so = s * 8;
            uint32_t afr[2][4];
            #pragma unroll
            for (int mt = 0; mt < 2; mt++) {
                int r0 = wm*32 + mt*16 + gid;
                afr[mt][0] = xb[r0*GRS + so + tg];
                afr[mt][1] = xb[(r0+8)*GRS + so + tg];
                afr[mt][2] = xb[r0*GRS + so + 4 + tg];
                afr[mt][3] = xb[(r0+8)*GRS + so + 4 + tg];
            }
            uint32_t bfr[8][2];
            #pragma unroll
            for (int nt = 0; nt < 8; nt++) {
                int nr = wn*64 + nt*8 + gid;
                bfr[nt][0] = wb[nr*GRS + so + tg];
                bfr[nt][1] = wb[nr*GRS + so + 4 + tg];
            }
            #pragma unroll
            for (int mt = 0; mt < 2; mt++)
                #pragma unroll
                for (int nt = 0; nt < 8; nt++)
                    mma_bf16(acc[mt][nt], afr[mt], bfr[nt]);
        }
    }

    __syncthreads();
    #pragma unroll
    for (int mt = 0; mt < 2; mt++) {
        int m0 = bm + wm*32 + mt*16 + gid;
        int row0 = remap ? ((m0 & (Tq-1)) * Bq + (m0 >> 9)) : m0;
        int m1 = m0 + 8;
        int row1 = remap ? ((m1 & (Tq-1)) * Bq + (m1 >> 9)) : m1;
        #pragma unroll
        for (int nt = 0; nt < 8; nt++) {
            int c0 = bn + wn*64 + nt*8 + tg*2;
            float2 bv = *(const float2*)(bias + c0);
            float2 o0, o1;
            o0.x = acc[mt][nt][0] + bv.x; o0.y = acc[mt][nt][1] + bv.y;
            o1.x = acc[mt][nt][2] + bv.x; o1.y = acc[mt][nt][3] + bv.y;
            *(float2*)(Y + (size_t)row0 * Gq + c0) = o0;
            *(float2*)(Y + (size_t)row1 * Gq + c0) = o1;
        }
    }
}

// ============================================================
// Distributed-flag grid barrier: per-block flag 128B apart,
// monotonic target values (replay-safe via per-launch base).
// Arrival = 1 release store; wait = 128 parallel L2 polls.
// ============================================================
__device__ __forceinline__ void gridbar_flags(int bid, unsigned target)
{
    __syncthreads();
    if (threadIdx.x == 0) {
        __threadfence();
        *(volatile unsigned*)&g_flags[bid * 32] = target;
    }
    if (threadIdx.x < NBLK) {
        while (*(volatile unsigned*)&g_flags[threadIdx.x * 32] < target) { }
        __threadfence();
    }
    __syncthreads();
}

// ============================================================
// Persistent LSTM layer with bf16 tensor-core recurrent GEMM.
// 128 blocks x 256 threads. Whh slice bf16 in smem; h (bf16)
// streamed in 2 chunks of 512k, double-buffered cp.async.
// Warp tile 32m x 16n, 2-way k-split; fp32 partial reduce.
// Distributed-flag barrier per step.
// ============================================================
__global__ void __launch_bounds__(256, 1)
lstm_layer(const float* __restrict__ xproj, const float* __restrict__ Whh,
           const float* __restrict__ bhh, float* __restrict__ hsf,
           __nv_bfloat16* __restrict__ hsb)
{
    extern __shared__ uint32_t sm2[];
    uint32_t* Wsm = sm2 + WOFF2;       // [32][WSTR]
    uint32_t* Hsm = sm2 + HOFF2;       // [2][64][HCH]
    float*    Rsm = (float*)(sm2 + ROFF2);   // [2][64][36]

    const int tid = threadIdx.x;
    const int bid = blockIdx.x;
    const int j0  = bid * 8;

    // per-launch barrier base (own flag: all blocks completed the same count)
    const unsigned base = *(volatile unsigned*)&g_flags[bid * 32];
    unsigned bcnt = 0;

    // ---- preload + convert weight slice to bf16 smem
    #pragma unroll
    for (int l = 0; l < 32; l++) {
        int idx = tid + l * 256;
        int c  = idx >> 8;
        int kq = idx & 255;
        int grow = (c >> 3) * Hq + j0 + (c & 7);
        float4 v = *(const float4*)(Whh + (size_t)grow * Hq + kq * 4);
        __nv_bfloat162 p0 = __floats2bfloat162_rn(v.x, v.y);
        __nv_bfloat162 p1 = __floats2bfloat162_rn(v.z, v.w);
        Wsm[c * WSTR + kq * 2]     = *(const uint32_t*)&p0;
        Wsm[c * WSTR + kq * 2 + 1] = *(const uint32_t*)&p1;
    }

    const int warp = tid >> 5;
    const int lane = tid & 31;
    const int gid = lane >> 2;
    const int tg  = lane & 3;
    const int ks  = warp & 1;
    const int wn2 = (warp >> 1) & 1;
    const int wm  = warp >> 2;

    float creg[2] = {0.0f, 0.0f};
    float bh[2][4];
    #pragma unroll
    for (int q = 0; q < 2; q++) {
        int p = tid + q * 256;
        int jl = p & 7;
        #pragma unroll
        for (int g2 = 0; g2 < 4; g2++) bh[q][g2] = bhh[g2 * Hq + j0 + jl];
    }

    ((uint32_t*)g_hbufb[0])[bid * 256 + tid] = 0u;
    bcnt++;
    gridbar_flags(bid, base + bcnt);

    for (int t = 0; t < Tq; t++) {
        const __nv_bfloat16* hprev = g_hbufb[t & 1];
        __nv_bfloat16* hnext = g_hbufb[(t + 1) & 1];

        // prefetch chunk 0 (64 rows x 512 bf16) into buf 0
        #pragma unroll
        for (int l = 0; l < 16; l++) {
            int idx = tid + l * 256;
            int row = idx >> 6;
            int seg = idx & 63;
            cp_async16(Hsm + row * HCH + seg * 4,
                       hprev + (size_t)row * Hq + seg * 8);
        }
        cp_commit();

        // prefetch this step's xproj gate values
        float xg[2][4];
        #pragma unroll
        for (int q = 0; q < 2; q++) {
            int p = tid + q * 256;
            int b = p >> 3, jl = p & 7;
            size_t xb = ((size_t)t * Bq + b) * Gq + j0 + jl;
            #pragma unroll
            for (int g2 = 0; g2 < 4; g2++) xg[q][g2] = xproj[xb + (size_t)g2 * Hq];
        }

        float acc[2][2][4] = {};
        for (int kc = 0; kc < 2; kc++) {
            const int buf = kc & 1;
            cp_wait0();
            __syncthreads();
            if (kc == 0) {
                uint32_t* hdst = Hsm + HCHBUF;
                #pragma unroll
                for (int l = 0; l < 16; l++) {
                    int idx = tid + l * 256;
                    int row = idx >> 6;
                    int seg = idx & 63;
                    cp_async16(hdst + row * HCH + seg * 4,
                               hprev + (size_t)row * Hq + 512 + seg * 8);
                }
                cp_commit();
            }

            const uint32_t* hb = Hsm + buf * HCHBUF;
            #pragma unroll
            for (int step = 0; step < 16; step++) {
                int kwc = ks * 128 + step * 8;
                int kww = kc * 256 + kwc;
                uint32_t afr[2][4];
                #pragma unroll
                for (int mt = 0; mt < 2; mt++) {
                    int r0 = wm * 32 + mt * 16 + gid;
                    afr[mt][0] = hb[r0 * HCH + kwc + tg];
                    afr[mt][1] = hb[(r0 + 8) * HCH + kwc + tg];
                    afr[mt][2] = hb[r0 * HCH + kwc + 4 + tg];
                    afr[mt][3] = hb[(r0 + 8) * HCH + kwc + 4 + tg];
                }
                uint32_t bfr[2][2];
                #pragma unroll
                for (int nt = 0; nt < 2; nt++) {
                    int nr = wn2 * 16 + nt * 8 + gid;
                    bfr[nt][0] = Wsm[nr * WSTR + kww + tg];
                    bfr[nt][1] = Wsm[nr * WSTR + kww + 4 + tg];
                }
                #pragma unroll
                for (int mt = 0; mt < 2; mt++)
                    #pragma unroll
                    for (int nt = 0; nt < 2; nt++)
                        mma_bf16(acc[mt][nt], afr[mt], bfr[nt]);
            }
        }

        // stash fp32 partials: Rsm[ks][row][col]
        #pragma unroll
        for (int mt = 0; mt < 2; mt++) {
            int r = wm * 32 + mt * 16 + gid;
            #pragma unroll
            for (int nt = 0; nt < 2; nt++) {
                int c = wn2 * 16 + nt * 8 + tg * 2;
                Rsm[ks * 2304 + r * 36 + c]           = acc[mt][nt][0];
                Rsm[ks * 2304 + r * 36 + c + 1]       = acc[mt][nt][1];
                Rsm[ks * 2304 + (r + 8) * 36 + c]     = acc[mt][nt][2];
                Rsm[ks * 2304 + (r + 8) * 36 + c + 1] = acc[mt][nt][3];
            }
        }
        __syncthreads();

        // pointwise LSTM update (2 items per thread)
        #pragma unroll
        for (int q = 0; q < 2; q++) {
            int p = tid + q * 256;
            int b = p >> 3, jl = p & 7;
            const float* r0p = Rsm + b * 36;
            const float* r1p = Rsm + 2304 + b * 36;
            float gi = r0p[jl]      + r1p[jl]      + xg[q][0] + bh[q][0];
            float gf = r0p[8 + jl]  + r1p[8 + jl]  + xg[q][1] + bh[q][1];
            float gg = r0p[16 + jl] + r1p[16 + jl] + xg[q][2] + bh[q][2];
            float go = r0p[24 + jl] + r1p[24 + jl] + xg[q][3] + bh[q][3];
            float ig = 1.0f / (1.0f + expf(-gi));
            float fg = 1.0f / (1.0f + expf(-gf));
            float gv = tanhf(gg);
            float og = 1.0f / (1.0f + expf(-go));
            float cn = fg * creg[q] + ig * gv;
            creg[q] = cn;
            float hn = og * tanhf(cn);
            hnext[(size_t)b * Hq + j0 + jl] = __float2bfloat16(hn);
            size_t so = ((size_t)t * Bq + b) * Hq + j0 + jl;
            if (hsf) hsf[so] = hn;
            if (hsb) hsb[so] = __float2bfloat16(hn);
        }
        bcnt++;
        gridbar_flags(bid, base + bcnt);
    }
}

// ============================================================
// Emissions: e[(t*B+b), c] = h2_row . fc_w[c] + fc_b[c]; one warp/row.
// ============================================================
__global__ void emis_kernel(const float* __restrict__ h2, const float* __restrict__ fcw,
                            const float* __restrict__ fcb, float* __restrict__ e)
{
    int warp = (blockIdx.x * blockDim.x + threadIdx.x) >> 5;
    int lane = threadIdx.x & 31;
    if (warp >= MTOT) return;
    const float* hr = h2 + (size_t)warp * Hq;
    float acc[Cq];
    #pragma unroll
    for (int cc = 0; cc < Cq; cc++) acc[cc] = 0.0f;
    for (int k = lane; k < Hq; k += 32) {
        float hv = hr[k];
        #pragma unroll
        for (int cc = 0; cc < Cq; cc++)
            acc[cc] = fmaf(hv, fcw[cc*Hq + k], acc[cc]);
    }
    #pragma unroll
    for (int cc = 0; cc < Cq; cc++) {
        float v = acc[cc];
        #pragma unroll
        for (int off = 16; off; off >>= 1) v += __shfl_down_sync(0xffffffffu, v, off);
        if (lane == 0) e[(size_t)warp * Cq + cc] = v + fcb[cc];
    }
}

// ============================================================
// CRF NLL per batch element. One warp per b. emissions in (T,B,C).
// ============================================================
__global__ void crf_kernel(const float* __restrict__ e, const int* __restrict__ labels,
                           const float* __restrict__ startt, const float* __restrict__ endt,
                           const float* __restrict__ trans, float* __restrict__ llh)
{
    int b = blockIdx.x;
    int lane = threadIdx.x;
    const int* lb = labels + (size_t)b * Tq;

    // ---- path score ----
    float part = 0.0f;
    int cnt = 0;
    for (int t = 1 + lane; t < Tq; t += 32) {
        int tag  = lb[t];
        int tagp = lb[t-1];
        if (tag != -1)
            part += trans[tagp*Cq + tag] + e[((size_t)t*Bq + b)*Cq + tag];
    }
    for (int t = lane; t < Tq; t += 32) cnt += (lb[t] != -1);
    #pragma unroll
    for (int off = 16; off; off >>= 1) {
        part += __shfl_down_sync(0xffffffffu, part, off);
        cnt  += __shfl_down_sync(0xffffffffu, cnt, off);
    }
    float score = 0.0f;
    if (lane == 0) {
        int tag0 = lb[0];
        score = startt[tag0] + e[(size_t)b*Cq + tag0] + part;
        int last = cnt - 1;
        score += endt[lb[last]];
    }

    // ---- logZ (forward algorithm) ----
    __shared__ float alpha[Cq];
    float tcol[Cq];
    if (lane < Cq) {
        #pragma unroll
        for (int cc = 0; cc < Cq; cc++) tcol[cc] = trans[cc*Cq + lane];
        alpha[lane] = startt[lane] + e[(size_t)b*Cq + lane];
    }
    __syncwarp();
    for (int t = 1; t < Tq; t++) {
        bool m = (lb[t] != -1);
        float av[Cq];
        #pragma unroll
        for (int cc = 0; cc < Cq; cc++) av[cc] = alpha[cc];
        float nxt = 0.0f;
        if (lane < Cq) {
            float mx = -1e30f;
            #pragma unroll
            for (int cc = 0; cc < Cq; cc++) mx = fmaxf(mx, av[cc] + tcol[cc]);
            float s = 0.0f;
            #pragma unroll
            for (int cc = 0; cc < Cq; cc++) s += expf(av[cc] + tcol[cc] - mx);
            nxt = mx + logf(s) + e[((size_t)t*Bq + b)*Cq + lane];
        }
        __syncwarp();
        if (m && lane < Cq) alpha[lane] = nxt;
        __syncwarp();
    }
    float v = (lane < Cq) ? alpha[lane] + endt[lane] : -1e30f;
    float mx = v;
    #pragma unroll
    for (int off = 16; off; off >>= 1) mx = fmaxf(mx, __shfl_xor_sync(0xffffffffu, mx, off));
    float sv = (lane < Cq) ? expf(v - mx) : 0.0f;
    #pragma unroll
    for (int off = 16; off; off >>= 1) sv += __shfl_xor_sync(0xffffffffu, sv, off);
    if (lane == 0) llh[b] = score - (mx + logf(sv));
}

__global__ void finalize_kernel(const float* __restrict__ llh, float* __restrict__ out)
{
    __shared__ float s[64];
    int lane = threadIdx.x;
    s[lane] = llh[lane];
    __syncthreads();
    #pragma unroll
    for (int off = 32; off; off >>= 1) {
        if (lane < off) s[lane] += s[lane + off];
        __syncthreads();
    }
    if (lane == 0) out[0] = -s[0] / (float)Bq;
}

// ============================================================
extern "C" void kernel_launch(void* const* d_in, const int* in_sizes, int n_in,
                              void* d_out, int out_size)
{
    const float* x     = (const float*)d_in[0];
    const int*   labels= (const int*)  d_in[1];
    // d_in[2] = lengths (unused; reference derives mask from labels)
    const float* Wih0  = (const float*)d_in[3];
    const float* Whh0  = (const float*)d_in[4];
    const float* bih0  = (const float*)d_in[5];
    const float* bhh0  = (const float*)d_in[6];
    const float* Wih1  = (const float*)d_in[7];
    const float* Whh1  = (const float*)d_in[8];
    const float* bih1  = (const float*)d_in[9];
    const float* bhh1  = (const float*)d_in[10];
    const float* fcw   = (const float*)d_in[11];
    const float* fcb   = (const float*)d_in[12];
    const float* startt= (const float*)d_in[13];
    const float* endt  = (const float*)d_in[14];
    const float* trans = (const float*)d_in[15];

    float *xproj, *hseq2, *emis, *llh;
    __nv_bfloat16 *xb, *wb;
    cudaGetSymbolAddress((void**)&xproj, g_xproj);
    cudaGetSymbolAddress((void**)&hseq2, g_hseq2);
    cudaGetSymbolAddress((void**)&xb,    g_xb);
    cudaGetSymbolAddress((void**)&wb,    g_wb);
    cudaGetSymbolAddress((void**)&emis,  g_emis);
    cudaGetSymbolAddress((void**)&llh,   g_llh);

    cudaFuncSetAttribute(lstm_layer, cudaFuncAttributeMaxDynamicSharedMemorySize, LSTM_SMEM_BYTES);
    cudaFuncSetAttribute(sgemm_bf16, cudaFuncAttributeMaxDynamicSharedMemorySize, GEMM_SMEM_BYTES);

    dim3 gsX(Gq/128, MTOT/128);      // (32, 256)

    // ---- layer 1 ----
    cvt_bf16<<<(MTOT*Iq/4 + 255)/256, 256>>>(x, xb, MTOT*Iq/4);
    cvt_bf16<<<(Gq*Iq/4 + 255)/256, 256>>>(Wih0, wb, Gq*Iq/4);
    sgemm_bf16<<<gsX, 256, GEMM_SMEM_BYTES>>>(xb, wb, bih0, xproj, Iq, /*remap=*/1);
    lstm_layer<<<NBLK, 256, LSTM_SMEM_BYTES>>>(xproj, Whh0, bhh0, (float*)nullptr, xb);

    // ---- layer 2 ----
    cvt_bf16<<<(Gq*Hq/4 + 255)/256, 256>>>(Wih1, wb, Gq*Hq/4);
    sgemm_bf16<<<gsX, 256, GEMM_SMEM_BYTES>>>(xb, wb, bih1, xproj, Hq, /*remap=*/0);
    lstm_layer<<<NBLK, 256, LSTM_SMEM_BYTES>>>(xproj, Whh1, bhh1, hseq2, (__nv_bfloat16*)nullptr);

    // ---- emissions + CRF ----
    emis_kernel<<<(MTOT*32)/256, 256>>>(hseq2, fcw, fcb, emis);
    crf_kernel<<<Bq, 32>>>(emis, labels, startt, endt, trans, llh);
    finalize_kernel<<<1, 64>>>(llh, (float*)d_out);
}